// round 1
// baseline (speedup 1.0000x reference)
#include <cuda_runtime.h>
#include <cuda_bf16.h>
#include <cstdio>

// ---------------------------------------------------------------------------
// Problem constants
// ---------------------------------------------------------------------------
#define BATCH   8
#define DIM     256
#define HEADS   8
#define CH      32            // DIM/HEADS
#define HW      4096          // 64*64
#define QKV_C   768           // 3*DIM
#define HIDDEN  307           // int(256*1.2)

// ---------------------------------------------------------------------------
// Scratch buffers (static device globals; no runtime allocation)
// ---------------------------------------------------------------------------
__device__ float g_qkv    [(size_t)BATCH * QKV_C * HW];   // 1x1 conv result
__device__ float g_qkvdw  [(size_t)BATCH * QKV_C * HW];   // after depthwise 3x3
__device__ float g_sumsq  [BATCH * 2 * DIM];              // sum of squares for q,k channels
__device__ float g_attn   [BATCH * HEADS * CH * CH];      // softmaxed attention
__device__ float g_attnout[(size_t)BATCH * DIM * HW];     // attention output
__device__ float g_hidden [(size_t)BATCH * HIDDEN * HW];  // mlp hidden

// ---------------------------------------------------------------------------
// GELU (tanh approximation -- matches jax.nn.gelu default approximate=True)
// ---------------------------------------------------------------------------
__device__ __forceinline__ float gelu_tanh(float x) {
    float x3 = x * x * x;
    return 0.5f * x * (1.0f + tanhf(0.7978845608028654f * (x + 0.044715f * x3)));
}

// ---------------------------------------------------------------------------
// Generic batched SGEMM:  C[b] = A(MxK) @ B[b](KxN)   (+ epilogue)
//   EPI 0: plain store
//   EPI 1: C = A@B + Res            (proj + residual)
//   EPI 2: C = gelu(A@B + bias)     (mlp1)
//   EPI 3: C = A@B + bias + Res     (mlp2 + residual; Res may alias C)
// 128x128 tile, ktile 8, 256 threads, 8x8 microtile.
// ---------------------------------------------------------------------------
template <int EPI>
__global__ __launch_bounds__(256)
void sgemm_kernel(const float* __restrict__ A, const float* __restrict__ Bg,
                  float* __restrict__ Cg, const float* __restrict__ bias,
                  const float* __restrict__ Resg, int M, int N, int K)
{
    const int batch = blockIdx.z;
    const float* B = Bg + (size_t)batch * K * N;
    float* C       = Cg + (size_t)batch * M * N;
    const float* R = (EPI == 1 || EPI == 3) ? (Resg + (size_t)batch * M * N) : nullptr;

    const int m0 = blockIdx.y * 128;
    const int n0 = blockIdx.x * 128;

    __shared__ float as[8][128];
    __shared__ float bs[8][128];

    const int tid = threadIdx.x;
    const int tx = tid & 15;     // 16 cols of threads
    const int ty = tid >> 4;     // 16 rows of threads

    float acc[8][8];
#pragma unroll
    for (int i = 0; i < 8; i++)
#pragma unroll
        for (int j = 0; j < 8; j++) acc[i][j] = 0.f;

    const int numKT = (K + 7) >> 3;
    for (int kt = 0; kt < numKT; ++kt) {
        const int kb = kt * 8;
        __syncthreads();
        // load A tile [128 m x 8 k] -> as[k][m]
#pragma unroll
        for (int i = tid; i < 1024; i += 256) {
            int m = i >> 3, k = i & 7;
            int gm = m0 + m, gk = kb + k;
            as[k][m] = (gm < M && gk < K) ? A[(size_t)gm * K + gk] : 0.f;
        }
        // load B tile [8 k x 128 n] -> bs[k][n]  (coalesced along n)
#pragma unroll
        for (int i = tid; i < 1024; i += 256) {
            int k = i >> 7, n = i & 127;
            int gk = kb + k;
            bs[k][n] = (gk < K) ? B[(size_t)gk * N + n0 + n] : 0.f;
        }
        __syncthreads();

#pragma unroll
        for (int k = 0; k < 8; ++k) {
            float a[8], bv[8];
#pragma unroll
            for (int i = 0; i < 4; i++) {
                a[i]      = as[k][ty * 4 + i];
                a[4 + i]  = as[k][64 + ty * 4 + i];
                bv[i]     = bs[k][tx * 4 + i];
                bv[4 + i] = bs[k][64 + tx * 4 + i];
            }
#pragma unroll
            for (int i = 0; i < 8; i++)
#pragma unroll
                for (int j = 0; j < 8; j++)
                    acc[i][j] = fmaf(a[i], bv[j], acc[i][j]);
        }
    }

    // epilogue
#pragma unroll
    for (int i = 0; i < 8; i++) {
        int gm = m0 + ((i < 4) ? (ty * 4 + i) : (64 + ty * 4 + (i - 4)));
        if (gm >= M) continue;
        float bi = 0.f;
        if (EPI == 2 || EPI == 3) bi = bias[gm];
#pragma unroll
        for (int j = 0; j < 8; j++) {
            int gn = n0 + ((j < 4) ? (tx * 4 + j) : (64 + tx * 4 + (j - 4)));
            float v = acc[i][j];
            if (EPI == 1) v += R[(size_t)gm * N + gn];
            if (EPI == 2) v = gelu_tanh(v + bi);
            if (EPI == 3) v += bi + R[(size_t)gm * N + gn];
            C[(size_t)gm * N + gn] = v;
        }
    }
}

// ---------------------------------------------------------------------------
// Zero a small buffer
// ---------------------------------------------------------------------------
__global__ void zero_kernel(float* p, int n)
{
    int i = blockIdx.x * blockDim.x + threadIdx.x;
    if (i < n) p[i] = 0.f;
}

// ---------------------------------------------------------------------------
// Depthwise 3x3 conv (stride 1, pad 1, cross-correlation like XLA) on g_qkv,
// fused with per-(b,channel) sum-of-squares for q,k channels (ch < 512).
// grid: (HW/256, BATCH*QKV_C), block: 256
// ---------------------------------------------------------------------------
__global__ __launch_bounds__(256)
void dwconv_kernel(const float* __restrict__ in, const float* __restrict__ w,
                   float* __restrict__ out, float* __restrict__ sumsq)
{
    const int bc = blockIdx.y;              // b*768 + ch
    const int b  = bc / QKV_C;
    const int ch = bc - b * QKV_C;
    const int n  = blockIdx.x * 256 + threadIdx.x;
    const int h  = n >> 6;
    const int wi = n & 63;

    const float* ip = in + (size_t)bc * HW;
    const float* wp = w + ch * 9;

    float acc = 0.f;
#pragma unroll
    for (int dh = 0; dh < 3; dh++) {
        int hh = h + dh - 1;
        if (hh < 0 || hh > 63) continue;
#pragma unroll
        for (int dw = 0; dw < 3; dw++) {
            int ww = wi + dw - 1;
            if (ww < 0 || ww > 63) continue;
            acc = fmaf(wp[dh * 3 + dw], ip[hh * 64 + ww], acc);
        }
    }
    out[(size_t)bc * HW + n] = acc;

    if (ch < 2 * DIM) {
        float v2 = acc * acc;
#pragma unroll
        for (int o = 16; o; o >>= 1) v2 += __shfl_down_sync(0xffffffffu, v2, o);
        __shared__ float red[8];
        if ((threadIdx.x & 31) == 0) red[threadIdx.x >> 5] = v2;
        __syncthreads();
        if (threadIdx.x == 0) {
            float s = 0.f;
#pragma unroll
            for (int i = 0; i < 8; i++) s += red[i];
            atomicAdd(&sumsq[b * (2 * DIM) + ch], s);
        }
    }
}

// ---------------------------------------------------------------------------
// Attention logits + temperature + softmax.
// One block per (b, head). S[c,d] = <q_c, k_d> / (||q_c|| ||k_d||) * T,
// then row softmax. 256 threads; thread (c = tid&31, g = tid>>5) owns
// S[c, 4g..4g+3]. q,k streamed through smem in 128-wide n tiles.
// ---------------------------------------------------------------------------
__global__ __launch_bounds__(256)
void attn_logits_kernel(const float* __restrict__ qkvdw,
                        const float* __restrict__ sumsq,
                        const float* __restrict__ temp,
                        float* __restrict__ attn)
{
    const int bh = blockIdx.x;
    const int b = bh >> 3, head = bh & 7;

    const float* qp = qkvdw + ((size_t)(b * QKV_C + head * CH)) * HW;
    const float* kp = qkvdw + ((size_t)(b * QKV_C + DIM + head * CH)) * HW;

    __shared__ float qs[32][129];
    __shared__ float ks[32][129];
    __shared__ float sm[32][33];

    const int tid = threadIdx.x;
    const int c = tid & 31;
    const int g = tid >> 5;

    float acc0 = 0.f, acc1 = 0.f, acc2 = 0.f, acc3 = 0.f;

    for (int t = 0; t < HW / 128; ++t) {
        const int n0 = t * 128;
        __syncthreads();
        for (int i = tid; i < 4096; i += 256) {
            int cc = i >> 7, j = i & 127;
            qs[cc][j] = qp[(size_t)cc * HW + n0 + j];
            ks[cc][j] = kp[(size_t)cc * HW + n0 + j];
        }
        __syncthreads();
        const int d0 = g * 4;
#pragma unroll 4
        for (int j = 0; j < 128; ++j) {
            float qv = qs[c][j];
            acc0 = fmaf(qv, ks[d0 + 0][j], acc0);
            acc1 = fmaf(qv, ks[d0 + 1][j], acc1);
            acc2 = fmaf(qv, ks[d0 + 2][j], acc2);
            acc3 = fmaf(qv, ks[d0 + 3][j], acc3);
        }
    }

    // scale by 1/max(||q||,eps) * 1/max(||k||,eps) * temperature
    const float* ssq = sumsq + b * (2 * DIM);
    const float fq = 1.0f / fmaxf(sqrtf(ssq[head * CH + c]), 1e-12f);
    const float T = temp[head];
    const int d0 = g * 4;
    float fk0 = 1.0f / fmaxf(sqrtf(ssq[DIM + head * CH + d0 + 0]), 1e-12f);
    float fk1 = 1.0f / fmaxf(sqrtf(ssq[DIM + head * CH + d0 + 1]), 1e-12f);
    float fk2 = 1.0f / fmaxf(sqrtf(ssq[DIM + head * CH + d0 + 2]), 1e-12f);
    float fk3 = 1.0f / fmaxf(sqrtf(ssq[DIM + head * CH + d0 + 3]), 1e-12f);
    sm[c][d0 + 0] = acc0 * fq * fk0 * T;
    sm[c][d0 + 1] = acc1 * fq * fk1 * T;
    sm[c][d0 + 2] = acc2 * fq * fk2 * T;
    sm[c][d0 + 3] = acc3 * fq * fk3 * T;
    __syncthreads();

    // softmax over d (rows of 32), one thread per row
    if (tid < 32) {
        float m = -1e30f;
#pragma unroll
        for (int d = 0; d < 32; d++) m = fmaxf(m, sm[tid][d]);
        float s = 0.f;
        float e[32];
#pragma unroll
        for (int d = 0; d < 32; d++) { e[d] = expf(sm[tid][d] - m); s += e[d]; }
        float inv = 1.0f / s;
        float* ap = attn + (size_t)bh * CH * CH + tid * CH;
#pragma unroll
        for (int d = 0; d < 32; d++) ap[d] = e[d] * inv;
    }
}

// ---------------------------------------------------------------------------
// Apply attention: out[c,n] = sum_d attn[c,d] * v[d,n]
// grid: (HW/512, BATCH*HEADS); each thread handles 2 spatial positions.
// ---------------------------------------------------------------------------
__global__ __launch_bounds__(256)
void attn_apply_kernel(const float* __restrict__ qkvdw,
                       const float* __restrict__ attn,
                       float* __restrict__ out)
{
    const int bh = blockIdx.y;
    const int b = bh >> 3, head = bh & 7;

    __shared__ float a[32][32];
    for (int i = threadIdx.x; i < 1024; i += 256)
        a[i >> 5][i & 31] = attn[(size_t)bh * 1024 + i];
    __syncthreads();

    const float* vp = qkvdw + ((size_t)(b * QKV_C + 2 * DIM + head * CH)) * HW;
    float* op = out + ((size_t)(b * DIM + head * CH)) * HW;

#pragma unroll
    for (int rep = 0; rep < 2; rep++) {
        const int n = blockIdx.x * 512 + rep * 256 + threadIdx.x;
        float o[32];
#pragma unroll
        for (int c = 0; c < 32; c++) o[c] = 0.f;
#pragma unroll
        for (int d = 0; d < 32; d++) {
            float vv = vp[(size_t)d * HW + n];
#pragma unroll
            for (int c = 0; c < 32; c++) o[c] = fmaf(a[c][d], vv, o[c]);
        }
#pragma unroll
        for (int c = 0; c < 32; c++) op[(size_t)c * HW + n] = o[c];
    }
}

// ---------------------------------------------------------------------------
// Launch
// ---------------------------------------------------------------------------
extern "C" void kernel_launch(void* const* d_in, const int* in_sizes, int n_in,
                              void* d_out, int out_size)
{
    const float* x      = (const float*)d_in[0];
    const float* w_qkv  = (const float*)d_in[1];
    const float* w_dw   = (const float*)d_in[2];
    const float* temp   = (const float*)d_in[3];
    const float* w_proj = (const float*)d_in[4];
    const float* w_mlp1 = (const float*)d_in[5];
    const float* b_mlp1 = (const float*)d_in[6];
    const float* w_mlp2 = (const float*)d_in[7];
    const float* b_mlp2 = (const float*)d_in[8];
    float* out = (float*)d_out;

    float *qkv, *qkvdw, *sumsq, *attn, *attnout, *hidden;
    cudaGetSymbolAddress((void**)&qkv,     g_qkv);
    cudaGetSymbolAddress((void**)&qkvdw,   g_qkvdw);
    cudaGetSymbolAddress((void**)&sumsq,   g_sumsq);
    cudaGetSymbolAddress((void**)&attn,    g_attn);
    cudaGetSymbolAddress((void**)&attnout, g_attnout);
    cudaGetSymbolAddress((void**)&hidden,  g_hidden);

    // 1) qkv = conv1x1(x, w_qkv):  [768,256] @ [256,4096] per batch
    sgemm_kernel<0><<<dim3(HW / 128, QKV_C / 128, BATCH), 256>>>(
        w_qkv, x, qkv, nullptr, nullptr, QKV_C, HW, DIM);

    // 2) zero sumsq
    zero_kernel<<<dim3((BATCH * 2 * DIM + 255) / 256), 256>>>(sumsq, BATCH * 2 * DIM);

    // 3) depthwise 3x3 + fused q/k sum-of-squares
    dwconv_kernel<<<dim3(HW / 256, BATCH * QKV_C), 256>>>(qkv, w_dw, qkvdw, sumsq);

    // 4) attention logits + softmax (norms folded in)
    attn_logits_kernel<<<dim3(BATCH * HEADS), 256>>>(qkvdw, sumsq, temp, attn);

    // 5) apply attention to v
    attn_apply_kernel<<<dim3(HW / 512, BATCH * HEADS), 256>>>(qkvdw, attn, attnout);

    // 6) x1 = x + conv1x1(attnout, w_proj)   -> d_out
    sgemm_kernel<1><<<dim3(HW / 128, (DIM + 127) / 128, BATCH), 256>>>(
        w_proj, attnout, out, nullptr, x, DIM, HW, DIM);

    // 7) hidden = gelu(conv1x1(x1, w_mlp1) + b1)
    sgemm_kernel<2><<<dim3(HW / 128, (HIDDEN + 127) / 128, BATCH), 256>>>(
        w_mlp1, out, hidden, b_mlp1, nullptr, HIDDEN, HW, DIM);

    // 8) d_out = x1 + conv1x1(hidden, w_mlp2) + b2   (in place on d_out)
    sgemm_kernel<3><<<dim3(HW / 128, (DIM + 127) / 128, BATCH), 256>>>(
        w_mlp2, hidden, out, b_mlp2, out, DIM, HW, HIDDEN);
}

// round 2
// speedup vs baseline: 1.4938x; 1.4938x over previous
#include <cuda_runtime.h>
#include <cuda_bf16.h>

// ---------------------------------------------------------------------------
// Problem constants
// ---------------------------------------------------------------------------
#define BATCH   8
#define DIM     256
#define HEADS   8
#define CH      32            // DIM/HEADS
#define HW      4096          // 64*64
#define QKV_C   768           // 3*DIM
#define HIDDEN  307           // int(256*1.2)
#define HID_PAD 320           // HIDDEN padded to mult of 16 (K of mlp2)
#define M1_PAD  384           // HIDDEN padded to mult of 128 (M of mlp1)

// ---------------------------------------------------------------------------
// Scratch buffers (static device globals; no runtime allocation)
// ---------------------------------------------------------------------------
__device__ float g_qkv    [(size_t)BATCH * QKV_C * HW];
__device__ float g_qkvdw  [(size_t)BATCH * QKV_C * HW];
__device__ float g_ssqp   [BATCH * 2 * DIM * 16];          // per-chunk sum-of-squares
__device__ float g_part   [BATCH * HEADS * 8 * CH * CH];   // partial logits (8 splits)
__device__ float g_attn   [BATCH * HEADS * CH * CH];
__device__ float g_attnout[(size_t)BATCH * DIM * HW];
__device__ float g_hidden [(size_t)BATCH * HID_PAD * HW];  // padded K rows for mlp2
__device__ float g_w1p    [M1_PAD * DIM];                  // w_mlp1 padded to 384 rows
__device__ float g_w2p    [DIM * HID_PAD];                 // w_mlp2 padded to 320 cols

// ---------------------------------------------------------------------------
__device__ __forceinline__ float gelu_tanh(float x) {
    float x3 = x * x * x;
    return 0.5f * x * (1.0f + tanhf(0.7978845608028654f * (x + 0.044715f * x3)));
}

// ---------------------------------------------------------------------------
// prep: build padded weight copies + zero the hidden pad rows
// ---------------------------------------------------------------------------
#define PREP_N1 (M1_PAD * DIM)                 // 98304
#define PREP_N2 (DIM * HID_PAD)                // 81920
#define PREP_N3 (BATCH * (HID_PAD - HIDDEN) * HW)  // 425984
__global__ void prep_kernel(const float* __restrict__ w1,
                            const float* __restrict__ w2,
                            float* __restrict__ w1p,
                            float* __restrict__ w2p,
                            float* __restrict__ hidden)
{
    int i = blockIdx.x * blockDim.x + threadIdx.x;
    if (i < PREP_N1) {
        int r = i >> 8;                              // /DIM
        w1p[i] = (r < HIDDEN) ? w1[i] : 0.f;         // same layout (row-major [r][256])
        return;
    }
    i -= PREP_N1;
    if (i < PREP_N2) {
        int r = i / HID_PAD, c = i - r * HID_PAD;
        w2p[i] = (c < HIDDEN) ? w2[r * HIDDEN + c] : 0.f;
        return;
    }
    i -= PREP_N2;
    if (i < PREP_N3) {
        int per_b = (HID_PAD - HIDDEN) * HW;         // 13*4096
        int b = i / per_b, rem = i - b * per_b;
        hidden[(size_t)b * HID_PAD * HW + (size_t)HIDDEN * HW + rem] = 0.f;
    }
}

// ---------------------------------------------------------------------------
// SGEMM: C[b] = A(MxK) @ B[b](KxN)  + epilogue.
// BM=BN=128, BK=16, 256 threads, 8x8 microtile, double-buffered smem,
// register-staged global loads (float4), ONE syncthreads per k-tile.
// Requirements (guaranteed by caller): K%16==0, N%128==0, A has >= gridDim.y*128
// rows allocated (padded), B/C/Res rows per contract below.
//   EPI 0: C = A@B
//   EPI 1: C = A@B + Res
//   EPI 2: C = gelu(A@B + bias)
//   EPI 3: C = A@B + bias + Res   (Res may alias C)
// ---------------------------------------------------------------------------
template <int EPI>
__global__ __launch_bounds__(256, 2)
void sgemm_kernel(const float* __restrict__ A, const float* __restrict__ Bg,
                  float* __restrict__ Cg, const float* __restrict__ bias,
                  const float* __restrict__ Resg,
                  int M, int N, int K, int MstrideC)
{
    const int batch = blockIdx.z;
    const float* B = Bg + (size_t)batch * K * N;
    float* C       = Cg + (size_t)batch * MstrideC * N;
    const float* R = (EPI == 1 || EPI == 3) ? (Resg + (size_t)batch * M * N) : nullptr;

    const int m0 = blockIdx.y * 128;
    const int n0 = blockIdx.x * 128;

    __shared__ float as[2][16][132];   // transposed A tile, padded
    __shared__ float bs[2][16][128];

    const int tid = threadIdx.x;
    const int tx = tid & 15;
    const int ty = tid >> 4;

    // staging decode (A: 512 float4 slots; B: 512 float4 slots)
    const int sA0 = tid, sA1 = tid + 256;
    const int amA0 = sA0 >> 2, akA0 = (sA0 & 3) * 4;
    const int amA1 = sA1 >> 2, akA1 = (sA1 & 3) * 4;
    const int bkB0 = sA0 >> 5, bnB0 = (sA0 & 31) * 4;
    const int bkB1 = sA1 >> 5, bnB1 = (sA1 & 31) * 4;

    float4 ra0, ra1, rb0, rb1;

    const int numKT = K >> 4;

    // preload tile 0
    {
        ra0 = *(const float4*)&A[(size_t)(m0 + amA0) * K + akA0];
        ra1 = *(const float4*)&A[(size_t)(m0 + amA1) * K + akA1];
        rb0 = *(const float4*)&B[(size_t)bkB0 * N + n0 + bnB0];
        rb1 = *(const float4*)&B[(size_t)bkB1 * N + n0 + bnB1];
        as[0][(sA0 & 3) * 4 + 0][amA0] = ra0.x;
        as[0][(sA0 & 3) * 4 + 1][amA0] = ra0.y;
        as[0][(sA0 & 3) * 4 + 2][amA0] = ra0.z;
        as[0][(sA0 & 3) * 4 + 3][amA0] = ra0.w;
        as[0][(sA1 & 3) * 4 + 0][amA1] = ra1.x;
        as[0][(sA1 & 3) * 4 + 1][amA1] = ra1.y;
        as[0][(sA1 & 3) * 4 + 2][amA1] = ra1.z;
        as[0][(sA1 & 3) * 4 + 3][amA1] = ra1.w;
        *(float4*)&bs[0][bkB0][bnB0] = rb0;
        *(float4*)&bs[0][bkB1][bnB1] = rb1;
    }
    __syncthreads();

    float acc[8][8];
#pragma unroll
    for (int i = 0; i < 8; i++)
#pragma unroll
        for (int j = 0; j < 8; j++) acc[i][j] = 0.f;

    for (int kt = 0; kt < numKT; ++kt) {
        const int buf = kt & 1;
        if (kt + 1 < numKT) {
            const int kb = (kt + 1) << 4;
            ra0 = *(const float4*)&A[(size_t)(m0 + amA0) * K + kb + akA0];
            ra1 = *(const float4*)&A[(size_t)(m0 + amA1) * K + kb + akA1];
            rb0 = *(const float4*)&B[(size_t)(kb + bkB0) * N + n0 + bnB0];
            rb1 = *(const float4*)&B[(size_t)(kb + bkB1) * N + n0 + bnB1];
        }
#pragma unroll
        for (int k = 0; k < 16; ++k) {
            float4 a0 = *(const float4*)&as[buf][k][ty * 4];
            float4 a1 = *(const float4*)&as[buf][k][64 + ty * 4];
            float4 b0 = *(const float4*)&bs[buf][k][tx * 4];
            float4 b1 = *(const float4*)&bs[buf][k][64 + tx * 4];
            float av[8] = {a0.x, a0.y, a0.z, a0.w, a1.x, a1.y, a1.z, a1.w};
            float bv[8] = {b0.x, b0.y, b0.z, b0.w, b1.x, b1.y, b1.z, b1.w};
#pragma unroll
            for (int i = 0; i < 8; i++)
#pragma unroll
                for (int j = 0; j < 8; j++)
                    acc[i][j] = fmaf(av[i], bv[j], acc[i][j]);
        }
        if (kt + 1 < numKT) {
            const int nb = buf ^ 1;
            as[nb][(sA0 & 3) * 4 + 0][amA0] = ra0.x;
            as[nb][(sA0 & 3) * 4 + 1][amA0] = ra0.y;
            as[nb][(sA0 & 3) * 4 + 2][amA0] = ra0.z;
            as[nb][(sA0 & 3) * 4 + 3][amA0] = ra0.w;
            as[nb][(sA1 & 3) * 4 + 0][amA1] = ra1.x;
            as[nb][(sA1 & 3) * 4 + 1][amA1] = ra1.y;
            as[nb][(sA1 & 3) * 4 + 2][amA1] = ra1.z;
            as[nb][(sA1 & 3) * 4 + 3][amA1] = ra1.w;
            *(float4*)&bs[nb][bkB0][bnB0] = rb0;
            *(float4*)&bs[nb][bkB1][bnB1] = rb1;
        }
        __syncthreads();
    }

    // epilogue (vectorized)
#pragma unroll
    for (int i = 0; i < 8; i++) {
        const int gm = m0 + ((i < 4) ? (ty * 4 + i) : (64 + ty * 4 + (i - 4)));
        if (gm >= M) continue;
        float bi = 0.f;
        if (EPI == 2 || EPI == 3) bi = bias[gm];
#pragma unroll
        for (int jh = 0; jh < 2; jh++) {
            const int gn = n0 + jh * 64 + tx * 4;
            float4 v;
            v.x = acc[i][jh * 4 + 0];
            v.y = acc[i][jh * 4 + 1];
            v.z = acc[i][jh * 4 + 2];
            v.w = acc[i][jh * 4 + 3];
            if (EPI == 1 || EPI == 3) {
                float4 r = *(const float4*)&R[(size_t)gm * N + gn];
                if (EPI == 3) { v.x += bi; v.y += bi; v.z += bi; v.w += bi; }
                v.x += r.x; v.y += r.y; v.z += r.z; v.w += r.w;
            }
            if (EPI == 2) {
                v.x = gelu_tanh(v.x + bi);
                v.y = gelu_tanh(v.y + bi);
                v.z = gelu_tanh(v.z + bi);
                v.w = gelu_tanh(v.w + bi);
            }
            *(float4*)&C[(size_t)gm * N + gn] = v;
        }
    }
}

// ---------------------------------------------------------------------------
// Depthwise 3x3 conv + per-(b,ch,chunk) sum-of-squares partials for q,k.
// grid: (16 chunks of 256 px, BATCH*QKV_C), block 256.
// ---------------------------------------------------------------------------
__global__ __launch_bounds__(256)
void dwconv_kernel(const float* __restrict__ in, const float* __restrict__ w,
                   float* __restrict__ out, float* __restrict__ ssqp)
{
    const int bc = blockIdx.y;
    const int b  = bc / QKV_C;
    const int ch = bc - b * QKV_C;
    const int n  = blockIdx.x * 256 + threadIdx.x;
    const int h  = n >> 6;
    const int wi = n & 63;

    const float* ip = in + (size_t)bc * HW;
    const float* wp = w + ch * 9;

    float acc = 0.f;
#pragma unroll
    for (int dh = 0; dh < 3; dh++) {
        int hh = h + dh - 1;
        if (hh < 0 || hh > 63) continue;
#pragma unroll
        for (int dw = 0; dw < 3; dw++) {
            int ww = wi + dw - 1;
            if (ww < 0 || ww > 63) continue;
            acc = fmaf(wp[dh * 3 + dw], ip[hh * 64 + ww], acc);
        }
    }
    out[(size_t)bc * HW + n] = acc;

    if (ch < 2 * DIM) {
        float v2 = acc * acc;
#pragma unroll
        for (int o = 16; o; o >>= 1) v2 += __shfl_down_sync(0xffffffffu, v2, o);
        __shared__ float red[8];
        if ((threadIdx.x & 31) == 0) red[threadIdx.x >> 5] = v2;
        __syncthreads();
        if (threadIdx.x == 0) {
            float s = 0.f;
#pragma unroll
            for (int i = 0; i < 8; i++) s += red[i];
            ssqp[(b * 2 * DIM + ch) * 16 + blockIdx.x] = s;
        }
    }
}

// ---------------------------------------------------------------------------
// Partial attention logits: grid (8 splits, 64 bh). Each block accumulates
// 32x32 raw dot products over a 512-column chunk; no scaling.
// ---------------------------------------------------------------------------
__global__ __launch_bounds__(256)
void attn_partial_kernel(const float* __restrict__ qkvdw, float* __restrict__ part)
{
    const int split = blockIdx.x;
    const int bh = blockIdx.y;
    const int b = bh >> 3, head = bh & 7;

    const float* qp = qkvdw + ((size_t)(b * QKV_C + head * CH)) * HW;
    const float* kp = qkvdw + ((size_t)(b * QKV_C + DIM + head * CH)) * HW;

    __shared__ float qs[32][129];
    __shared__ float ks[32][129];

    const int tid = threadIdx.x;
    const int c = tid & 31;
    const int d0 = (tid >> 5) * 4;

    float acc0 = 0.f, acc1 = 0.f, acc2 = 0.f, acc3 = 0.f;

    for (int t = 0; t < 4; ++t) {
        const int n0 = split * 512 + t * 128;
        __syncthreads();
        for (int i = tid; i < 4096; i += 256) {
            int cc = i >> 7, j = i & 127;
            qs[cc][j] = qp[(size_t)cc * HW + n0 + j];
            ks[cc][j] = kp[(size_t)cc * HW + n0 + j];
        }
        __syncthreads();
#pragma unroll 4
        for (int j = 0; j < 128; ++j) {
            float qv = qs[c][j];
            acc0 = fmaf(qv, ks[d0 + 0][j], acc0);
            acc1 = fmaf(qv, ks[d0 + 1][j], acc1);
            acc2 = fmaf(qv, ks[d0 + 2][j], acc2);
            acc3 = fmaf(qv, ks[d0 + 3][j], acc3);
        }
    }

    float* pp = part + ((size_t)(bh * 8 + split)) * (CH * CH) + c * CH + d0;
    pp[0] = acc0; pp[1] = acc1; pp[2] = acc2; pp[3] = acc3;
}

// ---------------------------------------------------------------------------
// Reduce partials, fold norms + temperature, softmax. grid 64, block 256.
// ---------------------------------------------------------------------------
__global__ __launch_bounds__(256)
void attn_softmax_kernel(const float* __restrict__ part,
                         const float* __restrict__ ssqp,
                         const float* __restrict__ temp,
                         float* __restrict__ attn)
{
    const int bh = blockIdx.x;
    const int b = bh >> 3, head = bh & 7;
    const int tid = threadIdx.x;

    __shared__ float S[32][33];
    __shared__ float fq[32], fk[32];

    if (tid < 64) {
        int isK = tid >> 5, c = tid & 31;
        int ch = isK ? (DIM + head * CH + c) : (head * CH + c);
        const float* pp = ssqp + (b * 2 * DIM + ch) * 16;
        float s = 0.f;
#pragma unroll
        for (int i = 0; i < 16; i++) s += pp[i];
        float f = 1.0f / fmaxf(sqrtf(s), 1e-12f);
        if (isK) fk[c] = f; else fq[c] = f;
    }
    __syncthreads();

    const float T = temp[head];
#pragma unroll
    for (int r = 0; r < 4; r++) {
        int e = tid + r * 256;
        int c = e >> 5, d = e & 31;
        float s = 0.f;
#pragma unroll
        for (int p = 0; p < 8; p++) s += part[((size_t)(bh * 8 + p)) * (CH * CH) + e];
        S[c][d] = s * fq[c] * fk[d] * T;
    }
    __syncthreads();

    if (tid < 32) {
        float m = -1e30f;
#pragma unroll
        for (int d = 0; d < 32; d++) m = fmaxf(m, S[tid][d]);
        float sum = 0.f;
        float e[32];
#pragma unroll
        for (int d = 0; d < 32; d++) { e[d] = expf(S[tid][d] - m); sum += e[d]; }
        float inv = 1.0f / sum;
        float* ap = attn + (size_t)bh * CH * CH + tid * CH;
#pragma unroll
        for (int d = 0; d < 32; d++) ap[d] = e[d] * inv;
    }
}

// ---------------------------------------------------------------------------
// Apply attention: out[c,n] = sum_d attn[c,d] * v[d,n]
// ---------------------------------------------------------------------------
__global__ __launch_bounds__(256)
void attn_apply_kernel(const float* __restrict__ qkvdw,
                       const float* __restrict__ attn,
                       float* __restrict__ out)
{
    const int bh = blockIdx.y;
    const int b = bh >> 3, head = bh & 7;

    __shared__ float a[32][32];
    for (int i = threadIdx.x; i < 1024; i += 256)
        a[i >> 5][i & 31] = attn[(size_t)bh * 1024 + i];
    __syncthreads();

    const float* vp = qkvdw + ((size_t)(b * QKV_C + 2 * DIM + head * CH)) * HW;
    float* op = out + ((size_t)(b * DIM + head * CH)) * HW;

#pragma unroll
    for (int rep = 0; rep < 2; rep++) {
        const int n = blockIdx.x * 512 + rep * 256 + threadIdx.x;
        float o[32];
#pragma unroll
        for (int c = 0; c < 32; c++) o[c] = 0.f;
#pragma unroll
        for (int d = 0; d < 32; d++) {
            float vv = vp[(size_t)d * HW + n];
#pragma unroll
            for (int c = 0; c < 32; c++) o[c] = fmaf(a[c][d], vv, o[c]);
        }
#pragma unroll
        for (int c = 0; c < 32; c++) op[(size_t)c * HW + n] = o[c];
    }
}

// ---------------------------------------------------------------------------
extern "C" void kernel_launch(void* const* d_in, const int* in_sizes, int n_in,
                              void* d_out, int out_size)
{
    const float* x      = (const float*)d_in[0];
    const float* w_qkv  = (const float*)d_in[1];
    const float* w_dw   = (const float*)d_in[2];
    const float* temp   = (const float*)d_in[3];
    const float* w_proj = (const float*)d_in[4];
    const float* w_mlp1 = (const float*)d_in[5];
    const float* b_mlp1 = (const float*)d_in[6];
    const float* w_mlp2 = (const float*)d_in[7];
    const float* b_mlp2 = (const float*)d_in[8];
    float* out = (float*)d_out;

    float *qkv, *qkvdw, *ssqp, *part, *attn, *attnout, *hidden, *w1p, *w2p;
    cudaGetSymbolAddress((void**)&qkv,     g_qkv);
    cudaGetSymbolAddress((void**)&qkvdw,   g_qkvdw);
    cudaGetSymbolAddress((void**)&ssqp,    g_ssqp);
    cudaGetSymbolAddress((void**)&part,    g_part);
    cudaGetSymbolAddress((void**)&attn,    g_attn);
    cudaGetSymbolAddress((void**)&attnout, g_attnout);
    cudaGetSymbolAddress((void**)&hidden,  g_hidden);
    cudaGetSymbolAddress((void**)&w1p,     g_w1p);
    cudaGetSymbolAddress((void**)&w2p,     g_w2p);

    // 0) padded weight copies + hidden pad-row zeroing
    const int prepTotal = PREP_N1 + PREP_N2 + PREP_N3;
    prep_kernel<<<(prepTotal + 255) / 256, 256>>>(w_mlp1, w_mlp2, w1p, w2p, hidden);

    // 1) qkv = conv1x1(x, w_qkv)
    sgemm_kernel<0><<<dim3(HW / 128, QKV_C / 128, BATCH), 256>>>(
        w_qkv, x, qkv, nullptr, nullptr, QKV_C, HW, DIM, QKV_C);

    // 2) depthwise 3x3 + sumsq partials
    dwconv_kernel<<<dim3(16, BATCH * QKV_C), 256>>>(qkv, w_dw, qkvdw, ssqp);

    // 3) partial logits
    attn_partial_kernel<<<dim3(8, BATCH * HEADS), 256>>>(qkvdw, part);

    // 4) reduce + scale + softmax
    attn_softmax_kernel<<<dim3(BATCH * HEADS), 256>>>(part, ssqp, temp, attn);

    // 5) apply attention to v
    attn_apply_kernel<<<dim3(HW / 512, BATCH * HEADS), 256>>>(qkvdw, attn, attnout);

    // 6) x1 = x + conv1x1(attnout, w_proj)  -> d_out
    sgemm_kernel<1><<<dim3(HW / 128, DIM / 128, BATCH), 256>>>(
        w_proj, attnout, out, nullptr, x, DIM, HW, DIM, DIM);

    // 7) hidden = gelu(conv1x1(x1, w_mlp1) + b1)   (C rows padded to 320)
    sgemm_kernel<2><<<dim3(HW / 128, M1_PAD / 128, BATCH), 256>>>(
        w1p, out, hidden, b_mlp1, nullptr, HIDDEN, HW, DIM, HID_PAD);

    // 8) d_out = x1 + conv1x1(hidden, w_mlp2) + b2   (K padded to 320)
    sgemm_kernel<3><<<dim3(HW / 128, DIM / 128, BATCH), 256>>>(
        w2p, hidden, out, b_mlp2, out, DIM, HW, HID_PAD, DIM);
}

// round 3
// speedup vs baseline: 1.7592x; 1.1776x over previous
#include <cuda_runtime.h>
#include <cuda_bf16.h>
#include <cstdint>

// ---------------------------------------------------------------------------
#define BATCH   8
#define DIM     256
#define HEADS   8
#define CH      32
#define HW      4096
#define QKV_C   768
#define HIDDEN  307
#define HID_PAD 320
#define M1_PAD  384

typedef __nv_bfloat16 bf16;

// ---------------------------------------------------------------------------
// Scratch (static device globals)
// ---------------------------------------------------------------------------
__device__ bf16  g_xh   [(size_t)BATCH * DIM * HW];
__device__ bf16  g_xl   [(size_t)BATCH * DIM * HW];
__device__ bf16  g_wqkvh[QKV_C * DIM],  g_wqkvl[QKV_C * DIM];
__device__ bf16  g_wprjh[DIM * DIM],    g_wprjl[DIM * DIM];
__device__ bf16  g_w1h  [M1_PAD * DIM], g_w1l  [M1_PAD * DIM];
__device__ bf16  g_w2h  [DIM * HID_PAD],g_w2l  [DIM * HID_PAD];
__device__ float g_b1p  [M1_PAD];
__device__ float g_qkv  [(size_t)BATCH * QKV_C * HW];
__device__ float g_qkvdw[(size_t)BATCH * QKV_C * HW];
__device__ float g_ssqp [BATCH * 2 * DIM * 16];
__device__ float g_part [BATCH * HEADS * 8 * CH * CH];
__device__ float g_attn [BATCH * HEADS * CH * CH];
__device__ bf16  g_aoh  [(size_t)BATCH * DIM * HW];
__device__ bf16  g_aol  [(size_t)BATCH * DIM * HW];
__device__ bf16  g_outh [(size_t)BATCH * DIM * HW];
__device__ bf16  g_outl [(size_t)BATCH * DIM * HW];
__device__ bf16  g_hidh [(size_t)BATCH * M1_PAD * HW];
__device__ bf16  g_hidl [(size_t)BATCH * M1_PAD * HW];

// ---------------------------------------------------------------------------
__device__ __forceinline__ float gelu_tanh(float x) {
    float x3 = x * x * x;
    return 0.5f * x * (1.0f + tanhf(0.7978845608028654f * (x + 0.044715f * x3)));
}

__device__ __forceinline__ void split2(float v, bf16& h, bf16& l) {
    h = __float2bfloat16(v);
    l = __float2bfloat16(v - __bfloat162float(h));
}

// ---------------------------------------------------------------------------
// PTX wrappers
// ---------------------------------------------------------------------------
__device__ __forceinline__ void ldsm_x4(uint32_t& r0, uint32_t& r1, uint32_t& r2,
                                        uint32_t& r3, uint32_t addr) {
    asm volatile("ldmatrix.sync.aligned.m8n8.x4.shared.b16 {%0,%1,%2,%3}, [%4];"
                 : "=r"(r0), "=r"(r1), "=r"(r2), "=r"(r3) : "r"(addr));
}
__device__ __forceinline__ void ldsm_x2_t(uint32_t& r0, uint32_t& r1, uint32_t addr) {
    asm volatile("ldmatrix.sync.aligned.m8n8.x2.trans.shared.b16 {%0,%1}, [%2];"
                 : "=r"(r0), "=r"(r1) : "r"(addr));
}
__device__ __forceinline__ void mma16816(float* d, const uint32_t* a,
                                         uint32_t b0, uint32_t b1) {
    asm volatile(
        "mma.sync.aligned.m16n8k16.row.col.f32.bf16.bf16.f32 "
        "{%0,%1,%2,%3}, {%4,%5,%6,%7}, {%8,%9}, {%0,%1,%2,%3};"
        : "+f"(d[0]), "+f"(d[1]), "+f"(d[2]), "+f"(d[3])
        : "r"(a[0]), "r"(a[1]), "r"(a[2]), "r"(a[3]), "r"(b0), "r"(b1));
}

// ---------------------------------------------------------------------------
// prep: split all weights to bf16 hi/lo (with padding) + padded bias
// ---------------------------------------------------------------------------
#define PN1 (QKV_C * DIM)      // w_qkv
#define PN2 (DIM * DIM)        // w_proj
#define PN3 (M1_PAD * DIM)     // w_mlp1 padded rows
#define PN4 (DIM * HID_PAD)    // w_mlp2 padded cols
#define PN5 (M1_PAD)           // bias1 padded
__global__ void prep_kernel(const float* __restrict__ wqkv, const float* __restrict__ wprj,
                            const float* __restrict__ w1,   const float* __restrict__ w2,
                            const float* __restrict__ b1)
{
    int i = blockIdx.x * blockDim.x + threadIdx.x;
    if (i < PN1) { split2(wqkv[i], g_wqkvh[i], g_wqkvl[i]); return; }
    i -= PN1;
    if (i < PN2) { split2(wprj[i], g_wprjh[i], g_wprjl[i]); return; }
    i -= PN2;
    if (i < PN3) {
        int r = i >> 8;
        float v = (r < HIDDEN) ? w1[i] : 0.f;
        split2(v, g_w1h[i], g_w1l[i]); return;
    }
    i -= PN3;
    if (i < PN4) {
        int r = i / HID_PAD, c = i - r * HID_PAD;
        float v = (c < HIDDEN) ? w2[r * HIDDEN + c] : 0.f;
        split2(v, g_w2h[i], g_w2l[i]); return;
    }
    i -= PN4;
    if (i < PN5) g_b1p[i] = (i < HIDDEN) ? b1[i] : 0.f;
}

// x -> hi/lo bf16
__global__ void convx_kernel(const float* __restrict__ x)
{
    size_t i = (size_t)blockIdx.x * blockDim.x + threadIdx.x;
    if (i < (size_t)BATCH * DIM * HW) split2(x[i], g_xh[i], g_xl[i]);
}

// ---------------------------------------------------------------------------
// bf16x3 tensor-core GEMM: C[b] = A(MxK) @ B[b](KxN) + epilogue
// A = Ah+Al (row-major [M][K]), B = Bh+Bl ([K][N], batch stride bStride).
// CTA tile 128x128, 8 warps (4m x 2n), warp tile 32x64, k-chunk 16.
//   EPI 0 (QKV):  Cf = acc
//   EPI 1 (PROJ): v = acc + Res;  Cf = v; (Ch,Cl) = split(v)
//   EPI 2 (MLP1): v = gelu(acc + bias); (Ch,Cl) = split(v)
//   EPI 3 (MLP2): Cf = acc + bias + Res  (Res may alias Cf)
// ---------------------------------------------------------------------------
template <int EPI>
__global__ __launch_bounds__(256)
void hgemm_kernel(const bf16* __restrict__ Ah, const bf16* __restrict__ Al,
                  const bf16* __restrict__ Bhg, const bf16* __restrict__ Blg,
                  float* __restrict__ Cfg, bf16* __restrict__ Chg, bf16* __restrict__ Clg,
                  const float* __restrict__ bias, const float* __restrict__ Resg,
                  int M, int N, int K, int bStride, int mStrideC)
{
    const int batch = blockIdx.z;
    const bf16* Bh = Bhg + (size_t)batch * bStride;
    const bf16* Bl = Blg + (size_t)batch * bStride;
    const size_t cOff = (size_t)batch * mStrideC * N;

    const int m0 = blockIdx.y * 128;
    const int n0 = blockIdx.x * 128;

    __shared__ __align__(16) bf16 sA[2][2][128][24];   // [buf][hi/lo][m][k]
    __shared__ __align__(16) bf16 sB[2][2][16][136];   // [buf][hi/lo][k][n]

    const int tid  = threadIdx.x;
    const int lane = tid & 31;
    const int warp = tid >> 5;
    const int wm = warp & 3;
    const int wn = warp >> 2;

    const uint32_t sA0 = (uint32_t)__cvta_generic_to_shared(&sA[0][0][0][0]);
    const uint32_t sB0 = (uint32_t)__cvta_generic_to_shared(&sB[0][0][0][0]);
    const uint32_t A_PL = 128 * 24 * 2, A_BUF = 2 * A_PL;
    const uint32_t B_PL = 16 * 136 * 2, B_BUF = 2 * B_PL;

    // ldmatrix lane addresses
    const uint32_t aAddr = sA0 + ((wm * 32 + (lane & 15)) * 24) * 2 + ((lane >> 4) * 16);
    const uint32_t bAddr = sB0 + (((lane & 15) * 136) + wn * 64) * 2;

    // global staging mapping
    const int am = tid >> 1, ahalf = tid & 1;        // A: 8 bf16 per thread per plane
    const int bk = tid >> 4, bseg  = tid & 15;       // B: 8 bf16 per thread per plane
    const bf16* gAh = Ah + (size_t)(m0 + am) * K + ahalf * 8;
    const bf16* gAl = Al + (size_t)(m0 + am) * K + ahalf * 8;
    const bf16* gBh = Bh + (size_t)bk * N + n0 + bseg * 8;
    const bf16* gBl = Bl + (size_t)bk * N + n0 + bseg * 8;

    const int numKT = K >> 4;
    int4 rah, ral, rbh, rbl;

    // preload chunk 0
    rah = *(const int4*)gAh;
    ral = *(const int4*)gAl;
    rbh = *(const int4*)gBh;
    rbl = *(const int4*)gBl;
    *(int4*)&sA[0][0][am][ahalf * 8] = rah;
    *(int4*)&sA[0][1][am][ahalf * 8] = ral;
    *(int4*)&sB[0][0][bk][bseg * 8] = rbh;
    *(int4*)&sB[0][1][bk][bseg * 8] = rbl;
    __syncthreads();

    float acc[2][8][4];
#pragma unroll
    for (int i = 0; i < 2; i++)
#pragma unroll
        for (int j = 0; j < 8; j++)
#pragma unroll
            for (int q = 0; q < 4; q++) acc[i][j][q] = 0.f;

    for (int kt = 0; kt < numKT; ++kt) {
        const int buf = kt & 1;
        if (kt + 1 < numKT) {
            const int kb = (kt + 1) << 4;
            rah = *(const int4*)(gAh + kb);
            ral = *(const int4*)(gAl + kb);
            rbh = *(const int4*)(gBh + (size_t)kb * N);
            rbl = *(const int4*)(gBl + (size_t)kb * N);
        }

        // A fragments (hi & lo, both m-subtiles)
        uint32_t ah[2][4], al[2][4];
        {
            const uint32_t ab = aAddr + buf * A_BUF;
            ldsm_x4(ah[0][0], ah[0][1], ah[0][2], ah[0][3], ab);
            ldsm_x4(ah[1][0], ah[1][1], ah[1][2], ah[1][3], ab + 16 * 24 * 2);
            ldsm_x4(al[0][0], al[0][1], al[0][2], al[0][3], ab + A_PL);
            ldsm_x4(al[1][0], al[1][1], al[1][2], al[1][3], ab + A_PL + 16 * 24 * 2);
        }
        const uint32_t bb = bAddr + buf * B_BUF;
#pragma unroll
        for (int j = 0; j < 8; j++) {
            uint32_t bh0, bh1, bl0, bl1;
            ldsm_x2_t(bh0, bh1, bb + j * 16);
            ldsm_x2_t(bl0, bl1, bb + B_PL + j * 16);
#pragma unroll
            for (int i = 0; i < 2; i++) {
                mma16816(acc[i][j], ah[i], bh0, bh1);   // hi*hi
                mma16816(acc[i][j], ah[i], bl0, bl1);   // hi*lo
                mma16816(acc[i][j], al[i], bh0, bh1);   // lo*hi
            }
        }

        if (kt + 1 < numKT) {
            const int nb = buf ^ 1;
            *(int4*)&sA[nb][0][am][ahalf * 8] = rah;
            *(int4*)&sA[nb][1][am][ahalf * 8] = ral;
            *(int4*)&sB[nb][0][bk][bseg * 8] = rbh;
            *(int4*)&sB[nb][1][bk][bseg * 8] = rbl;
        }
        __syncthreads();
    }

    // epilogue
    float* Cf = (EPI != 2) ? (Cfg + cOff) : nullptr;
    bf16*  Chp = (EPI == 1 || EPI == 2) ? (Chg + cOff) : nullptr;
    bf16*  Clp = (EPI == 1 || EPI == 2) ? (Clg + cOff) : nullptr;
    const float* R = (EPI == 1 || EPI == 3) ? (Resg + cOff) : nullptr;

    const int g = lane >> 2, t = lane & 3;
#pragma unroll
    for (int i = 0; i < 2; i++) {
#pragma unroll
        for (int half = 0; half < 2; half++) {
            const int r = m0 + wm * 32 + i * 16 + half * 8 + g;
            float bi = 0.f;
            if (EPI == 2 || EPI == 3) bi = bias[r];
#pragma unroll
            for (int j = 0; j < 8; j++) {
                const int c = n0 + wn * 64 + j * 8 + t * 2;
                float v0 = acc[i][j][half * 2 + 0];
                float v1 = acc[i][j][half * 2 + 1];
                const size_t idx = (size_t)r * N + c;
                if (EPI == 0) {
                    Cf[idx] = v0; Cf[idx + 1] = v1;
                } else if (EPI == 1) {
                    v0 += R[idx]; v1 += R[idx + 1];
                    Cf[idx] = v0; Cf[idx + 1] = v1;
                    bf16 h0, l0, h1, l1;
                    split2(v0, h0, l0); split2(v1, h1, l1);
                    Chp[idx] = h0; Chp[idx + 1] = h1;
                    Clp[idx] = l0; Clp[idx + 1] = l1;
                } else if (EPI == 2) {
                    v0 = gelu_tanh(v0 + bi); v1 = gelu_tanh(v1 + bi);
                    bf16 h0, l0, h1, l1;
                    split2(v0, h0, l0); split2(v1, h1, l1);
                    Chp[idx] = h0; Chp[idx + 1] = h1;
                    Clp[idx] = l0; Clp[idx + 1] = l1;
                } else {
                    v0 += bi + R[idx]; v1 += bi + R[idx + 1];
                    Cf[idx] = v0; Cf[idx + 1] = v1;
                }
            }
        }
    }
}

// ---------------------------------------------------------------------------
// Depthwise 3x3 conv + per-(b,ch,chunk) sum-of-squares partials for q,k.
// ---------------------------------------------------------------------------
__global__ __launch_bounds__(256)
void dwconv_kernel(const float* __restrict__ in, const float* __restrict__ w,
                   float* __restrict__ out, float* __restrict__ ssqp)
{
    const int bc = blockIdx.y;
    const int b  = bc / QKV_C;
    const int ch = bc - b * QKV_C;
    const int n  = blockIdx.x * 256 + threadIdx.x;
    const int h  = n >> 6;
    const int wi = n & 63;

    const float* ip = in + (size_t)bc * HW;
    const float* wp = w + ch * 9;

    float acc = 0.f;
#pragma unroll
    for (int dh = 0; dh < 3; dh++) {
        int hh = h + dh - 1;
        if (hh < 0 || hh > 63) continue;
#pragma unroll
        for (int dw = 0; dw < 3; dw++) {
            int ww = wi + dw - 1;
            if (ww < 0 || ww > 63) continue;
            acc = fmaf(wp[dh * 3 + dw], ip[hh * 64 + ww], acc);
        }
    }
    out[(size_t)bc * HW + n] = acc;

    if (ch < 2 * DIM) {
        float v2 = acc * acc;
#pragma unroll
        for (int o = 16; o; o >>= 1) v2 += __shfl_down_sync(0xffffffffu, v2, o);
        __shared__ float red[8];
        if ((threadIdx.x & 31) == 0) red[threadIdx.x >> 5] = v2;
        __syncthreads();
        if (threadIdx.x == 0) {
            float s = 0.f;
#pragma unroll
            for (int i = 0; i < 8; i++) s += red[i];
            ssqp[(b * 2 * DIM + ch) * 16 + blockIdx.x] = s;
        }
    }
}

// ---------------------------------------------------------------------------
// Partial attention logits (raw dot products over a 512-col chunk)
// ---------------------------------------------------------------------------
__global__ __launch_bounds__(256)
void attn_partial_kernel(const float* __restrict__ qkvdw, float* __restrict__ part)
{
    const int split = blockIdx.x;
    const int bh = blockIdx.y;
    const int b = bh >> 3, head = bh & 7;

    const float* qp = qkvdw + ((size_t)(b * QKV_C + head * CH)) * HW;
    const float* kp = qkvdw + ((size_t)(b * QKV_C + DIM + head * CH)) * HW;

    __shared__ float qs[32][129];
    __shared__ float ks[32][129];

    const int tid = threadIdx.x;
    const int c = tid & 31;
    const int d0 = (tid >> 5) * 4;

    float acc0 = 0.f, acc1 = 0.f, acc2 = 0.f, acc3 = 0.f;

    for (int t = 0; t < 4; ++t) {
        const int n0 = split * 512 + t * 128;
        __syncthreads();
        for (int i = tid; i < 4096; i += 256) {
            int cc = i >> 7, j = i & 127;
            qs[cc][j] = qp[(size_t)cc * HW + n0 + j];
            ks[cc][j] = kp[(size_t)cc * HW + n0 + j];
        }
        __syncthreads();
#pragma unroll 4
        for (int j = 0; j < 128; ++j) {
            float qv = qs[c][j];
            acc0 = fmaf(qv, ks[d0 + 0][j], acc0);
            acc1 = fmaf(qv, ks[d0 + 1][j], acc1);
            acc2 = fmaf(qv, ks[d0 + 2][j], acc2);
            acc3 = fmaf(qv, ks[d0 + 3][j], acc3);
        }
    }

    float* pp = part + ((size_t)(bh * 8 + split)) * (CH * CH) + c * CH + d0;
    pp[0] = acc0; pp[1] = acc1; pp[2] = acc2; pp[3] = acc3;
}

// ---------------------------------------------------------------------------
// Reduce partials, fold norms + temperature, softmax.
// ---------------------------------------------------------------------------
__global__ __launch_bounds__(256)
void attn_softmax_kernel(const float* __restrict__ part,
                         const float* __restrict__ ssqp,
                         const float* __restrict__ temp,
                         float* __restrict__ attn)
{
    const int bh = blockIdx.x;
    const int b = bh >> 3, head = bh & 7;
    const int tid = threadIdx.x;

    __shared__ float S[32][33];
    __shared__ float fq[32], fk[32];

    if (tid < 64) {
        int isK = tid >> 5, c = tid & 31;
        int ch = isK ? (DIM + head * CH + c) : (head * CH + c);
        const float* pp = ssqp + (b * 2 * DIM + ch) * 16;
        float s = 0.f;
#pragma unroll
        for (int i = 0; i < 16; i++) s += pp[i];
        float f = 1.0f / fmaxf(sqrtf(s), 1e-12f);
        if (isK) fk[c] = f; else fq[c] = f;
    }
    __syncthreads();

    const float T = temp[head];
#pragma unroll
    for (int r = 0; r < 4; r++) {
        int e = tid + r * 256;
        int c = e >> 5, d = e & 31;
        float s = 0.f;
#pragma unroll
        for (int p = 0; p < 8; p++) s += part[((size_t)(bh * 8 + p)) * (CH * CH) + e];
        S[c][d] = s * fq[c] * fk[d] * T;
    }
    __syncthreads();

    if (tid < 32) {
        float m = -1e30f;
#pragma unroll
        for (int d = 0; d < 32; d++) m = fmaxf(m, S[tid][d]);
        float sum = 0.f;
        float e[32];
#pragma unroll
        for (int d = 0; d < 32; d++) { e[d] = expf(S[tid][d] - m); sum += e[d]; }
        float inv = 1.0f / sum;
        float* ap = attn + (size_t)bh * CH * CH + tid * CH;
#pragma unroll
        for (int d = 0; d < 32; d++) ap[d] = e[d] * inv;
    }
}

// ---------------------------------------------------------------------------
// Apply attention: out[c,n] = sum_d attn[c,d] * v[d,n]  -> bf16 hi/lo
// ---------------------------------------------------------------------------
__global__ __launch_bounds__(256)
void attn_apply_kernel(const float* __restrict__ qkvdw,
                       const float* __restrict__ attn,
                       bf16* __restrict__ outh, bf16* __restrict__ outl)
{
    const int bh = blockIdx.y;
    const int b = bh >> 3, head = bh & 7;

    __shared__ float a[32][32];
    for (int i = threadIdx.x; i < 1024; i += 256)
        a[i >> 5][i & 31] = attn[(size_t)bh * 1024 + i];
    __syncthreads();

    const float* vp = qkvdw + ((size_t)(b * QKV_C + 2 * DIM + head * CH)) * HW;
    const size_t obase = ((size_t)(b * DIM + head * CH)) * HW;

#pragma unroll
    for (int rep = 0; rep < 2; rep++) {
        const int n = blockIdx.x * 512 + rep * 256 + threadIdx.x;
        float o[32];
#pragma unroll
        for (int c = 0; c < 32; c++) o[c] = 0.f;
#pragma unroll
        for (int d = 0; d < 32; d++) {
            float vv = vp[(size_t)d * HW + n];
#pragma unroll
            for (int c = 0; c < 32; c++) o[c] = fmaf(a[c][d], vv, o[c]);
        }
#pragma unroll
        for (int c = 0; c < 32; c++) {
            bf16 h, l;
            split2(o[c], h, l);
            outh[obase + (size_t)c * HW + n] = h;
            outl[obase + (size_t)c * HW + n] = l;
        }
    }
}

// ---------------------------------------------------------------------------
extern "C" void kernel_launch(void* const* d_in, const int* in_sizes, int n_in,
                              void* d_out, int out_size)
{
    const float* x      = (const float*)d_in[0];
    const float* w_qkv  = (const float*)d_in[1];
    const float* w_dw   = (const float*)d_in[2];
    const float* temp   = (const float*)d_in[3];
    const float* w_proj = (const float*)d_in[4];
    const float* w_mlp1 = (const float*)d_in[5];
    const float* b_mlp1 = (const float*)d_in[6];
    const float* w_mlp2 = (const float*)d_in[7];
    const float* b_mlp2 = (const float*)d_in[8];
    float* out = (float*)d_out;

    bf16 *xh, *xl, *wqkvh, *wqkvl, *wprjh, *wprjl, *w1h, *w1l, *w2h, *w2l;
    bf16 *aoh, *aol, *outh, *outl, *hidh, *hidl;
    float *b1p, *qkv, *qkvdw, *ssqp, *part, *attn;
    cudaGetSymbolAddress((void**)&xh,    g_xh);
    cudaGetSymbolAddress((void**)&xl,    g_xl);
    cudaGetSymbolAddress((void**)&wqkvh, g_wqkvh);
    cudaGetSymbolAddress((void**)&wqkvl, g_wqkvl);
    cudaGetSymbolAddress((void**)&wprjh, g_wprjh);
    cudaGetSymbolAddress((void**)&wprjl, g_wprjl);
    cudaGetSymbolAddress((void**)&w1h,   g_w1h);
    cudaGetSymbolAddress((void**)&w1l,   g_w1l);
    cudaGetSymbolAddress((void**)&w2h,   g_w2h);
    cudaGetSymbolAddress((void**)&w2l,   g_w2l);
    cudaGetSymbolAddress((void**)&b1p,   g_b1p);
    cudaGetSymbolAddress((void**)&qkv,   g_qkv);
    cudaGetSymbolAddress((void**)&qkvdw, g_qkvdw);
    cudaGetSymbolAddress((void**)&ssqp,  g_ssqp);
    cudaGetSymbolAddress((void**)&part,  g_part);
    cudaGetSymbolAddress((void**)&attn,  g_attn);
    cudaGetSymbolAddress((void**)&aoh,   g_aoh);
    cudaGetSymbolAddress((void**)&aol,   g_aol);
    cudaGetSymbolAddress((void**)&outh,  g_outh);
    cudaGetSymbolAddress((void**)&outl,  g_outl);
    cudaGetSymbolAddress((void**)&hidh,  g_hidh);
    cudaGetSymbolAddress((void**)&hidl,  g_hidl);

    // 0) weight splits + padded bias; x split
    const int prepTotal = PN1 + PN2 + PN3 + PN4 + PN5;
    prep_kernel<<<(prepTotal + 255) / 256, 256>>>(w_qkv, w_proj, w_mlp1, w_mlp2, b_mlp1);
    const size_t xN = (size_t)BATCH * DIM * HW;
    convx_kernel<<<(int)((xN + 255) / 256), 256>>>(x);

    // 1) qkv = w_qkv @ x   (fp32 out for dwconv)
    hgemm_kernel<0><<<dim3(HW / 128, QKV_C / 128, BATCH), 256>>>(
        wqkvh, wqkvl, xh, xl, qkv, nullptr, nullptr, nullptr, nullptr,
        QKV_C, HW, DIM, DIM * HW, QKV_C);

    // 2) depthwise 3x3 + sumsq partials
    dwconv_kernel<<<dim3(16, BATCH * QKV_C), 256>>>(qkv, w_dw, qkvdw, ssqp);

    // 3) partial logits
    attn_partial_kernel<<<dim3(8, BATCH * HEADS), 256>>>(qkvdw, part);

    // 4) reduce + scale + softmax
    attn_softmax_kernel<<<dim3(BATCH * HEADS), 256>>>(part, ssqp, temp, attn);

    // 5) apply attention -> bf16 hi/lo
    attn_apply_kernel<<<dim3(HW / 512, BATCH * HEADS), 256>>>(qkvdw, attn, aoh, aol);

    // 6) x1 = x + w_proj @ attnout  -> d_out fp32 + hi/lo
    hgemm_kernel<1><<<dim3(HW / 128, DIM / 128, BATCH), 256>>>(
        wprjh, wprjl, aoh, aol, out, outh, outl, nullptr, x,
        DIM, HW, DIM, DIM * HW, DIM);

    // 7) hidden = gelu(w1 @ x1 + b1)  -> hi/lo only (padded rows -> gelu(0)=0)
    hgemm_kernel<2><<<dim3(HW / 128, M1_PAD / 128, BATCH), 256>>>(
        w1h, w1l, outh, outl, nullptr, hidh, hidl, b1p, nullptr,
        M1_PAD, HW, DIM, DIM * HW, M1_PAD);

    // 8) d_out = x1 + w2 @ hidden + b2  (in place, K padded to 320)
    hgemm_kernel<3><<<dim3(HW / 128, DIM / 128, BATCH), 256>>>(
        w2h, w2l, hidh, hidl, out, nullptr, nullptr, b_mlp2, out,
        DIM, HW, HID_PAD, M1_PAD * HW, DIM);
}

// round 4
// speedup vs baseline: 2.0579x; 1.1698x over previous
#include <cuda_runtime.h>
#include <cuda_bf16.h>
#include <cstdint>

// ---------------------------------------------------------------------------
#define BATCH   8
#define DIM     256
#define HEADS   8
#define CH      32
#define HW      4096
#define QKV_C   768
#define HIDDEN  307
#define HID_PAD 320
#define M1_PAD  384

typedef __nv_bfloat16 bf16;

// ---------------------------------------------------------------------------
// Scratch (static device globals)
// ---------------------------------------------------------------------------
__device__ bf16  g_wqkvh[QKV_C * DIM],  g_wqkvl[QKV_C * DIM];
__device__ bf16  g_wprjh[DIM * DIM],    g_wprjl[DIM * DIM];
__device__ bf16  g_w1h  [M1_PAD * DIM], g_w1l  [M1_PAD * DIM];
__device__ bf16  g_w2h  [DIM * HID_PAD],g_w2l  [DIM * HID_PAD];
__device__ float g_b1p  [M1_PAD];
__device__ float g_qkv  [(size_t)BATCH * QKV_C * HW];
__device__ float g_qkvdw[(size_t)BATCH * QKV_C * HW];
__device__ float g_ssq  [BATCH * 2 * DIM];
__device__ float g_part [BATCH * HEADS * 8 * CH * CH];
__device__ float g_attn [BATCH * HEADS * CH * CH];
__device__ bf16  g_aoh  [(size_t)BATCH * DIM * HW];
__device__ bf16  g_aol  [(size_t)BATCH * DIM * HW];
__device__ bf16  g_outh [(size_t)BATCH * DIM * HW];
__device__ bf16  g_outl [(size_t)BATCH * DIM * HW];
__device__ bf16  g_hidh [(size_t)BATCH * M1_PAD * HW];
__device__ bf16  g_hidl [(size_t)BATCH * M1_PAD * HW];

// ---------------------------------------------------------------------------
__device__ __forceinline__ float gelu_tanh(float x) {
    float x3 = x * x * x;
    return 0.5f * x * (1.0f + tanhf(0.7978845608028654f * (x + 0.044715f * x3)));
}
__device__ __forceinline__ void split2(float v, bf16& h, bf16& l) {
    h = __float2bfloat16(v);
    l = __float2bfloat16(v - __bfloat162float(h));
}

// ---------------------------------------------------------------------------
// PTX wrappers
// ---------------------------------------------------------------------------
__device__ __forceinline__ void ldsm_x4(uint32_t& r0, uint32_t& r1, uint32_t& r2,
                                        uint32_t& r3, uint32_t addr) {
    asm volatile("ldmatrix.sync.aligned.m8n8.x4.shared.b16 {%0,%1,%2,%3}, [%4];"
                 : "=r"(r0), "=r"(r1), "=r"(r2), "=r"(r3) : "r"(addr));
}
__device__ __forceinline__ void ldsm_x4_t(uint32_t& r0, uint32_t& r1, uint32_t& r2,
                                          uint32_t& r3, uint32_t addr) {
    asm volatile("ldmatrix.sync.aligned.m8n8.x4.trans.shared.b16 {%0,%1,%2,%3}, [%4];"
                 : "=r"(r0), "=r"(r1), "=r"(r2), "=r"(r3) : "r"(addr));
}
__device__ __forceinline__ void mma16816(float* d, const uint32_t* a,
                                         uint32_t b0, uint32_t b1) {
    asm volatile(
        "mma.sync.aligned.m16n8k16.row.col.f32.bf16.bf16.f32 "
        "{%0,%1,%2,%3}, {%4,%5,%6,%7}, {%8,%9}, {%0,%1,%2,%3};"
        : "+f"(d[0]), "+f"(d[1]), "+f"(d[2]), "+f"(d[3])
        : "r"(a[0]), "r"(a[1]), "r"(a[2]), "r"(a[3]), "r"(b0), "r"(b1));
}

// ---------------------------------------------------------------------------
// prep: split weights to bf16 hi/lo (with padding) + padded bias
// ---------------------------------------------------------------------------
#define PN1 (QKV_C * DIM)
#define PN2 (DIM * DIM)
#define PN3 (M1_PAD * DIM)
#define PN4 (DIM * HID_PAD)
#define PN5 (M1_PAD)
__global__ void prep_kernel(const float* __restrict__ wqkv, const float* __restrict__ wprj,
                            const float* __restrict__ w1,   const float* __restrict__ w2,
                            const float* __restrict__ b1)
{
    int i = blockIdx.x * blockDim.x + threadIdx.x;
    if (i < PN1) { split2(wqkv[i], g_wqkvh[i], g_wqkvl[i]); return; }
    i -= PN1;
    if (i < PN2) { split2(wprj[i], g_wprjh[i], g_wprjl[i]); return; }
    i -= PN2;
    if (i < PN3) {
        int r = i >> 8;
        float v = (r < HIDDEN) ? w1[i] : 0.f;
        split2(v, g_w1h[i], g_w1l[i]); return;
    }
    i -= PN3;
    if (i < PN4) {
        int r = i / HID_PAD, c = i - r * HID_PAD;
        float v = (c < HIDDEN) ? w2[r * HIDDEN + c] : 0.f;
        split2(v, g_w2h[i], g_w2l[i]); return;
    }
    i -= PN4;
    if (i < PN5) g_b1p[i] = (i < HIDDEN) ? b1[i] : 0.f;
}

// ---------------------------------------------------------------------------
// bf16x3 tensor-core GEMM: C[b] = A(MxK) @ B[b](KxN) + epilogue
// If SPLITB: B is fp32 and is split to hi/lo in-register during staging.
//   EPI 0 (QKV):  Cf = acc
//   EPI 1 (PROJ): v = acc + Res; Cf = v; (Ch,Cl) = split(v)
//   EPI 2 (MLP1): v = gelu(acc + bias); (Ch,Cl) = split(v)
//   EPI 3 (MLP2): Cf = acc + bias + Res  (Res may alias Cf)
// ---------------------------------------------------------------------------
template <int EPI, bool SPLITB>
__global__ __launch_bounds__(256)
void hgemm_kernel(const bf16* __restrict__ Ah, const bf16* __restrict__ Al,
                  const bf16* __restrict__ Bhg, const bf16* __restrict__ Blg,
                  const float* __restrict__ Bfg,
                  float* __restrict__ Cfg, bf16* __restrict__ Chg, bf16* __restrict__ Clg,
                  const float* __restrict__ bias, const float* __restrict__ Resg,
                  int M, int N, int K, int bStride, int mStrideC)
{
    const int batch = blockIdx.z;
    const size_t cOff = (size_t)batch * mStrideC * N;

    const int m0 = blockIdx.y * 128;
    const int n0 = blockIdx.x * 128;

    __shared__ __align__(16) bf16 sA[2][2][128][24];
    __shared__ __align__(16) bf16 sB[2][2][16][136];

    const int tid  = threadIdx.x;
    const int lane = tid & 31;
    const int warp = tid >> 5;
    const int wm = warp & 3;
    const int wn = warp >> 2;

    const uint32_t sA0 = (uint32_t)__cvta_generic_to_shared(&sA[0][0][0][0]);
    const uint32_t sB0 = (uint32_t)__cvta_generic_to_shared(&sB[0][0][0][0]);
    const uint32_t A_PL = 128 * 24 * 2, A_BUF = 2 * A_PL;
    const uint32_t B_PL = 16 * 136 * 2, B_BUF = 2 * B_PL;

    const uint32_t aAddr = sA0 + ((wm * 32 + (lane & 15)) * 24) * 2 + ((lane >> 4) * 16);
    // B ldmatrix.x4.trans: lanes 0-15 rows k0..15 (n-offset 0), lanes 16-31 same rows n-offset +8
    const uint32_t bAddr = sB0 + ((lane & 15) * 136 + wn * 64 + (lane >> 4) * 8) * 2;

    const int am = tid >> 1, ahalf = tid & 1;
    const int bk = tid >> 4, bseg  = tid & 15;
    const bf16* gAh = Ah + (size_t)(m0 + am) * K + ahalf * 8;
    const bf16* gAl = Al + (size_t)(m0 + am) * K + ahalf * 8;
    const bf16* gBh; const bf16* gBl; const float* gBf;
    if (SPLITB) {
        gBf = Bfg + (size_t)batch * bStride + (size_t)bk * N + n0 + bseg * 8;
    } else {
        gBh = Bhg + (size_t)batch * bStride + (size_t)bk * N + n0 + bseg * 8;
        gBl = Blg + (size_t)batch * bStride + (size_t)bk * N + n0 + bseg * 8;
    }

    const int numKT = K >> 4;
    int4 rah, ral, rbh, rbl;
    float4 rf0, rf1;

    // preload chunk 0
    rah = *(const int4*)gAh;
    ral = *(const int4*)gAl;
    if (SPLITB) { rf0 = *(const float4*)gBf; rf1 = *((const float4*)gBf + 1); }
    else        { rbh = *(const int4*)gBh;   rbl = *(const int4*)gBl; }
    *(int4*)&sA[0][0][am][ahalf * 8] = rah;
    *(int4*)&sA[0][1][am][ahalf * 8] = ral;
    if (SPLITB) {
        float f[8] = {rf0.x, rf0.y, rf0.z, rf0.w, rf1.x, rf1.y, rf1.z, rf1.w};
#pragma unroll
        for (int q = 0; q < 8; q++) {
            bf16 h, l; split2(f[q], h, l);
            sB[0][0][bk][bseg * 8 + q] = h;
            sB[0][1][bk][bseg * 8 + q] = l;
        }
    } else {
        *(int4*)&sB[0][0][bk][bseg * 8] = rbh;
        *(int4*)&sB[0][1][bk][bseg * 8] = rbl;
    }
    __syncthreads();

    float acc[2][8][4];
#pragma unroll
    for (int i = 0; i < 2; i++)
#pragma unroll
        for (int j = 0; j < 8; j++)
#pragma unroll
            for (int q = 0; q < 4; q++) acc[i][j][q] = 0.f;

    for (int kt = 0; kt < numKT; ++kt) {
        const int buf = kt & 1;
        if (kt + 1 < numKT) {
            const int kb = (kt + 1) << 4;
            rah = *(const int4*)(gAh + kb);
            ral = *(const int4*)(gAl + kb);
            if (SPLITB) {
                rf0 = *(const float4*)(gBf + (size_t)kb * N);
                rf1 = *((const float4*)(gBf + (size_t)kb * N) + 1);
            } else {
                rbh = *(const int4*)(gBh + (size_t)kb * N);
                rbl = *(const int4*)(gBl + (size_t)kb * N);
            }
        }

        uint32_t ah[2][4], al[2][4];
        {
            const uint32_t ab = aAddr + buf * A_BUF;
            ldsm_x4(ah[0][0], ah[0][1], ah[0][2], ah[0][3], ab);
            ldsm_x4(ah[1][0], ah[1][1], ah[1][2], ah[1][3], ab + 16 * 24 * 2);
            ldsm_x4(al[0][0], al[0][1], al[0][2], al[0][3], ab + A_PL);
            ldsm_x4(al[1][0], al[1][1], al[1][2], al[1][3], ab + A_PL + 16 * 24 * 2);
        }
        const uint32_t bb = bAddr + buf * B_BUF;
#pragma unroll
        for (int j2 = 0; j2 < 4; j2++) {
            uint32_t bh0, bh1, bh2, bh3, bl0, bl1, bl2, bl3;
            ldsm_x4_t(bh0, bh1, bh2, bh3, bb + j2 * 32);
            ldsm_x4_t(bl0, bl1, bl2, bl3, bb + B_PL + j2 * 32);
#pragma unroll
            for (int i = 0; i < 2; i++) {
                mma16816(acc[i][2 * j2],     ah[i], bh0, bh1);
                mma16816(acc[i][2 * j2],     ah[i], bl0, bl1);
                mma16816(acc[i][2 * j2],     al[i], bh0, bh1);
                mma16816(acc[i][2 * j2 + 1], ah[i], bh2, bh3);
                mma16816(acc[i][2 * j2 + 1], ah[i], bl2, bl3);
                mma16816(acc[i][2 * j2 + 1], al[i], bh2, bh3);
            }
        }

        if (kt + 1 < numKT) {
            const int nb = buf ^ 1;
            *(int4*)&sA[nb][0][am][ahalf * 8] = rah;
            *(int4*)&sA[nb][1][am][ahalf * 8] = ral;
            if (SPLITB) {
                float f[8] = {rf0.x, rf0.y, rf0.z, rf0.w, rf1.x, rf1.y, rf1.z, rf1.w};
#pragma unroll
                for (int q = 0; q < 8; q++) {
                    bf16 h, l; split2(f[q], h, l);
                    sB[nb][0][bk][bseg * 8 + q] = h;
                    sB[nb][1][bk][bseg * 8 + q] = l;
                }
            } else {
                *(int4*)&sB[nb][0][bk][bseg * 8] = rbh;
                *(int4*)&sB[nb][1][bk][bseg * 8] = rbl;
            }
        }
        __syncthreads();
    }

    // epilogue
    float* Cf = (EPI != 2) ? (Cfg + cOff) : nullptr;
    bf16*  Chp = (EPI == 1 || EPI == 2) ? (Chg + cOff) : nullptr;
    bf16*  Clp = (EPI == 1 || EPI == 2) ? (Clg + cOff) : nullptr;
    const float* R = (EPI == 1 || EPI == 3) ? (Resg + cOff) : nullptr;

    const int g = lane >> 2, t = lane & 3;
#pragma unroll
    for (int i = 0; i < 2; i++) {
#pragma unroll
        for (int half = 0; half < 2; half++) {
            const int r = m0 + wm * 32 + i * 16 + half * 8 + g;
            float bi = 0.f;
            if (EPI == 2 || EPI == 3) bi = bias[r];
#pragma unroll
            for (int j = 0; j < 8; j++) {
                const int c = n0 + wn * 64 + j * 8 + t * 2;
                float v0 = acc[i][j][half * 2 + 0];
                float v1 = acc[i][j][half * 2 + 1];
                const size_t idx = (size_t)r * N + c;
                if (EPI == 0) {
                    Cf[idx] = v0; Cf[idx + 1] = v1;
                } else if (EPI == 1) {
                    v0 += R[idx]; v1 += R[idx + 1];
                    Cf[idx] = v0; Cf[idx + 1] = v1;
                    bf16 h0, l0, h1, l1;
                    split2(v0, h0, l0); split2(v1, h1, l1);
                    Chp[idx] = h0; Chp[idx + 1] = h1;
                    Clp[idx] = l0; Clp[idx + 1] = l1;
                } else if (EPI == 2) {
                    v0 = gelu_tanh(v0 + bi); v1 = gelu_tanh(v1 + bi);
                    bf16 h0, l0, h1, l1;
                    split2(v0, h0, l0); split2(v1, h1, l1);
                    Chp[idx] = h0; Chp[idx + 1] = h1;
                    Clp[idx] = l0; Clp[idx + 1] = l1;
                } else {
                    v0 += bi + R[idx]; v1 += bi + R[idx + 1];
                    Cf[idx] = v0; Cf[idx + 1] = v1;
                }
            }
        }
    }
}

// ---------------------------------------------------------------------------
// Depthwise 3x3 conv, smem-tiled: one block per (b,ch) 64x64 plane.
// Zero halo (66x68 tile), 4-wide output groups, full-plane sumsq for q/k.
// ---------------------------------------------------------------------------
__global__ __launch_bounds__(256)
void dwconv_kernel(const float* __restrict__ in, const float* __restrict__ w,
                   float* __restrict__ out, float* __restrict__ ssq)
{
    const int bc = blockIdx.x;
    const int b  = bc / QKV_C;
    const int ch = bc - b * QKV_C;
    const int tid = threadIdx.x;

    __shared__ float t[66][68];
    __shared__ float red[8];

    // zero halo (rows 0,65; cols 0,65)
    if (tid < 264) {
        if (tid < 68)       t[0][tid] = 0.f;
        else if (tid < 136) t[65][tid - 68] = 0.f;
        else if (tid < 200) t[tid - 136 + 1][0] = 0.f;
        else                t[tid - 200 + 1][65] = 0.f;
    }

    // load plane (1024 float4)
    const float4* ip4 = (const float4*)(in + (size_t)bc * HW);
#pragma unroll
    for (int j = 0; j < 4; j++) {
        int idx = tid + j * 256;
        int h = idx >> 4, w4 = idx & 15;
        float4 v = ip4[idx];
        t[h + 1][w4 * 4 + 1] = v.x;
        t[h + 1][w4 * 4 + 2] = v.y;
        t[h + 1][w4 * 4 + 3] = v.z;
        t[h + 1][w4 * 4 + 4] = v.w;
    }

    const float* wp = w + ch * 9;
    float k0 = wp[0], k1 = wp[1], k2 = wp[2];
    float k3 = wp[3], k4 = wp[4], k5 = wp[5];
    float k6 = wp[6], k7 = wp[7], k8 = wp[8];
    __syncthreads();

    float4* op4 = (float4*)(out + (size_t)bc * HW);
    float ss = 0.f;

#pragma unroll
    for (int grp = 0; grp < 4; grp++) {
        const int n = grp * 1024 + tid * 4;
        const int h = n >> 6, w0 = n & 63;
        float s0 = 0.f, s1 = 0.f, s2 = 0.f, s3 = 0.f;
#pragma unroll
        for (int dh = 0; dh < 3; dh++) {
            const float* r = &t[h + dh][w0];
            float r0 = r[0], r1 = r[1], r2 = r[2], r3 = r[3], r4 = r[4], r5 = r[5];
            float ka = (dh == 0) ? k0 : (dh == 1) ? k3 : k6;
            float kb = (dh == 0) ? k1 : (dh == 1) ? k4 : k7;
            float kc = (dh == 0) ? k2 : (dh == 1) ? k5 : k8;
            s0 = fmaf(ka, r0, fmaf(kb, r1, fmaf(kc, r2, s0)));
            s1 = fmaf(ka, r1, fmaf(kb, r2, fmaf(kc, r3, s1)));
            s2 = fmaf(ka, r2, fmaf(kb, r3, fmaf(kc, r4, s2)));
            s3 = fmaf(ka, r3, fmaf(kb, r4, fmaf(kc, r5, s3)));
        }
        float4 o; o.x = s0; o.y = s1; o.z = s2; o.w = s3;
        op4[grp * 256 + tid] = o;
        ss += s0 * s0 + s1 * s1 + s2 * s2 + s3 * s3;
    }

    if (ch < 2 * DIM) {
#pragma unroll
        for (int o = 16; o; o >>= 1) ss += __shfl_down_sync(0xffffffffu, ss, o);
        if ((tid & 31) == 0) red[tid >> 5] = ss;
        __syncthreads();
        if (tid == 0) {
            float s = 0.f;
#pragma unroll
            for (int i = 0; i < 8; i++) s += red[i];
            ssq[b * 2 * DIM + ch] = s;
        }
    }
}

// ---------------------------------------------------------------------------
// Partial attention logits: K stored transposed [j][d] -> broadcast float4.
// ---------------------------------------------------------------------------
__global__ __launch_bounds__(256)
void attn_partial_kernel(const float* __restrict__ qkvdw, float* __restrict__ part)
{
    const int split = blockIdx.x;
    const int bh = blockIdx.y;
    const int b = bh >> 3, head = bh & 7;

    const float* qp = qkvdw + ((size_t)(b * QKV_C + head * CH)) * HW;
    const float* kp = qkvdw + ((size_t)(b * QKV_C + DIM + head * CH)) * HW;

    __shared__ float qs[32][129];
    __shared__ __align__(16) float ks[128][36];

    const int tid = threadIdx.x;
    const int c = tid & 31;
    const int d0 = (tid >> 5) * 4;

    float acc0 = 0.f, acc1 = 0.f, acc2 = 0.f, acc3 = 0.f;

    for (int t = 0; t < 4; ++t) {
        const int n0 = split * 512 + t * 128;
        __syncthreads();
        // stage q [c][j], k transposed [j][d]; float4 global loads
#pragma unroll
        for (int it = 0; it < 4; it++) {
            int idx = tid + it * 256;              // 0..1023 float4 slots
            int row = idx >> 5, j4 = idx & 31;
            float4 qv = *(const float4*)&qp[(size_t)row * HW + n0 + j4 * 4];
            qs[row][j4 * 4 + 0] = qv.x;
            qs[row][j4 * 4 + 1] = qv.y;
            qs[row][j4 * 4 + 2] = qv.z;
            qs[row][j4 * 4 + 3] = qv.w;
            float4 kv = *(const float4*)&kp[(size_t)row * HW + n0 + j4 * 4];
            ks[j4 * 4 + 0][row] = kv.x;
            ks[j4 * 4 + 1][row] = kv.y;
            ks[j4 * 4 + 2][row] = kv.z;
            ks[j4 * 4 + 3][row] = kv.w;
        }
        __syncthreads();
#pragma unroll 4
        for (int j = 0; j < 128; ++j) {
            float qv = qs[c][j];
            float4 kk = *(const float4*)&ks[j][d0];
            acc0 = fmaf(qv, kk.x, acc0);
            acc1 = fmaf(qv, kk.y, acc1);
            acc2 = fmaf(qv, kk.z, acc2);
            acc3 = fmaf(qv, kk.w, acc3);
        }
    }

    float* pp = part + ((size_t)(bh * 8 + split)) * (CH * CH) + c * CH + d0;
    pp[0] = acc0; pp[1] = acc1; pp[2] = acc2; pp[3] = acc3;
}

// ---------------------------------------------------------------------------
// Reduce partials, fold norms + temperature, softmax.
// ---------------------------------------------------------------------------
__global__ __launch_bounds__(256)
void attn_softmax_kernel(const float* __restrict__ part,
                         const float* __restrict__ ssq,
                         const float* __restrict__ temp,
                         float* __restrict__ attn)
{
    const int bh = blockIdx.x;
    const int b = bh >> 3, head = bh & 7;
    const int tid = threadIdx.x;

    __shared__ float S[32][33];
    __shared__ float fq[32], fk[32];

    if (tid < 64) {
        int isK = tid >> 5, c = tid & 31;
        int ch = isK ? (DIM + head * CH + c) : (head * CH + c);
        float s = ssq[b * 2 * DIM + ch];
        float f = 1.0f / fmaxf(sqrtf(s), 1e-12f);
        if (isK) fk[c] = f; else fq[c] = f;
    }
    __syncthreads();

    const float T = temp[head];
#pragma unroll
    for (int r = 0; r < 4; r++) {
        int e = tid + r * 256;
        int c = e >> 5, d = e & 31;
        float s = 0.f;
#pragma unroll
        for (int p = 0; p < 8; p++) s += part[((size_t)(bh * 8 + p)) * (CH * CH) + e];
        S[c][d] = s * fq[c] * fk[d] * T;
    }
    __syncthreads();

    if (tid < 32) {
        float m = -1e30f;
#pragma unroll
        for (int d = 0; d < 32; d++) m = fmaxf(m, S[tid][d]);
        float sum = 0.f;
        float e[32];
#pragma unroll
        for (int d = 0; d < 32; d++) { e[d] = expf(S[tid][d] - m); sum += e[d]; }
        float inv = 1.0f / sum;
        float* ap = attn + (size_t)bh * CH * CH + tid * CH;
#pragma unroll
        for (int d = 0; d < 32; d++) ap[d] = e[d] * inv;
    }
}

// ---------------------------------------------------------------------------
// Apply attention: out[c,n] = sum_d attn[c,d] * v[d,n]  -> bf16 hi/lo
// ---------------------------------------------------------------------------
__global__ __launch_bounds__(256)
void attn_apply_kernel(const float* __restrict__ qkvdw,
                       const float* __restrict__ attn,
                       bf16* __restrict__ outh, bf16* __restrict__ outl)
{
    const int bh = blockIdx.y;
    const int b = bh >> 3, head = bh & 7;

    __shared__ float a[32][32];
    for (int i = threadIdx.x; i < 1024; i += 256)
        a[i >> 5][i & 31] = attn[(size_t)bh * 1024 + i];
    __syncthreads();

    const float* vp = qkvdw + ((size_t)(b * QKV_C + 2 * DIM + head * CH)) * HW;
    const size_t obase = ((size_t)(b * DIM + head * CH)) * HW;

#pragma unroll
    for (int rep = 0; rep < 2; rep++) {
        const int n = blockIdx.x * 512 + rep * 256 + threadIdx.x;
        float o[32];
#pragma unroll
        for (int c = 0; c < 32; c++) o[c] = 0.f;
#pragma unroll
        for (int d = 0; d < 32; d++) {
            float vv = vp[(size_t)d * HW + n];
#pragma unroll
            for (int c = 0; c < 32; c++) o[c] = fmaf(a[c][d], vv, o[c]);
        }
#pragma unroll
        for (int c = 0; c < 32; c++) {
            bf16 h, l;
            split2(o[c], h, l);
            outh[obase + (size_t)c * HW + n] = h;
            outl[obase + (size_t)c * HW + n] = l;
        }
    }
}

// ---------------------------------------------------------------------------
extern "C" void kernel_launch(void* const* d_in, const int* in_sizes, int n_in,
                              void* d_out, int out_size)
{
    const float* x      = (const float*)d_in[0];
    const float* w_qkv  = (const float*)d_in[1];
    const float* w_dw   = (const float*)d_in[2];
    const float* temp   = (const float*)d_in[3];
    const float* w_proj = (const float*)d_in[4];
    const float* w_mlp1 = (const float*)d_in[5];
    const float* b_mlp1 = (const float*)d_in[6];
    const float* w_mlp2 = (const float*)d_in[7];
    const float* b_mlp2 = (const float*)d_in[8];
    float* out = (float*)d_out;

    bf16 *wqkvh, *wqkvl, *wprjh, *wprjl, *w1h, *w1l, *w2h, *w2l;
    bf16 *aoh, *aol, *outh, *outl, *hidh, *hidl;
    float *b1p, *qkv, *qkvdw, *ssq, *part, *attn;
    cudaGetSymbolAddress((void**)&wqkvh, g_wqkvh);
    cudaGetSymbolAddress((void**)&wqkvl, g_wqkvl);
    cudaGetSymbolAddress((void**)&wprjh, g_wprjh);
    cudaGetSymbolAddress((void**)&wprjl, g_wprjl);
    cudaGetSymbolAddress((void**)&w1h,   g_w1h);
    cudaGetSymbolAddress((void**)&w1l,   g_w1l);
    cudaGetSymbolAddress((void**)&w2h,   g_w2h);
    cudaGetSymbolAddress((void**)&w2l,   g_w2l);
    cudaGetSymbolAddress((void**)&b1p,   g_b1p);
    cudaGetSymbolAddress((void**)&qkv,   g_qkv);
    cudaGetSymbolAddress((void**)&qkvdw, g_qkvdw);
    cudaGetSymbolAddress((void**)&ssq,   g_ssq);
    cudaGetSymbolAddress((void**)&part,  g_part);
    cudaGetSymbolAddress((void**)&attn,  g_attn);
    cudaGetSymbolAddress((void**)&aoh,   g_aoh);
    cudaGetSymbolAddress((void**)&aol,   g_aol);
    cudaGetSymbolAddress((void**)&outh,  g_outh);
    cudaGetSymbolAddress((void**)&outl,  g_outl);
    cudaGetSymbolAddress((void**)&hidh,  g_hidh);
    cudaGetSymbolAddress((void**)&hidl,  g_hidl);

    // 0) weight splits + padded bias
    const int prepTotal = PN1 + PN2 + PN3 + PN4 + PN5;
    prep_kernel<<<(prepTotal + 255) / 256, 256>>>(w_qkv, w_proj, w_mlp1, w_mlp2, b_mlp1);

    // 1) qkv = w_qkv @ x  (x split in-register during staging)
    hgemm_kernel<0, true><<<dim3(HW / 128, QKV_C / 128, BATCH), 256>>>(
        wqkvh, wqkvl, nullptr, nullptr, x, qkv, nullptr, nullptr, nullptr, nullptr,
        QKV_C, HW, DIM, DIM * HW, QKV_C);

    // 2) depthwise 3x3 (smem-tiled) + full-plane sumsq
    dwconv_kernel<<<dim3(BATCH * QKV_C), 256>>>(qkv, w_dw, qkvdw, ssq);

    // 3) partial logits
    attn_partial_kernel<<<dim3(8, BATCH * HEADS), 256>>>(qkvdw, part);

    // 4) reduce + scale + softmax
    attn_softmax_kernel<<<dim3(BATCH * HEADS), 256>>>(part, ssq, temp, attn);

    // 5) apply attention -> bf16 hi/lo
    attn_apply_kernel<<<dim3(HW / 512, BATCH * HEADS), 256>>>(qkvdw, attn, aoh, aol);

    // 6) x1 = x + w_proj @ attnout -> d_out fp32 + hi/lo
    hgemm_kernel<1, false><<<dim3(HW / 128, DIM / 128, BATCH), 256>>>(
        wprjh, wprjl, aoh, aol, nullptr, out, outh, outl, nullptr, x,
        DIM, HW, DIM, DIM * HW, DIM);

    // 7) hidden = gelu(w1 @ x1 + b1) -> hi/lo
    hgemm_kernel<2, false><<<dim3(HW / 128, M1_PAD / 128, BATCH), 256>>>(
        w1h, w1l, outh, outl, nullptr, nullptr, hidh, hidl, b1p, nullptr,
        M1_PAD, HW, DIM, DIM * HW, M1_PAD);

    // 8) d_out = x1 + w2 @ hidden + b2  (in place)
    hgemm_kernel<3, false><<<dim3(HW / 128, DIM / 128, BATCH), 256>>>(
        w2h, w2l, hidh, hidl, nullptr, out, nullptr, nullptr, b_mlp2, out,
        DIM, HW, HID_PAD, M1_PAD * HW, DIM);
}

// round 5
// speedup vs baseline: 2.8183x; 1.3695x over previous
#include <cuda_runtime.h>
#include <cuda_bf16.h>
#include <cstdint>

// ---------------------------------------------------------------------------
#define BATCH   8
#define DIM     256
#define HEADS   8
#define CH      32
#define HW      4096
#define QKV_C   768
#define HIDDEN  307
#define HID_PAD 320
#define M1_PAD  384

typedef __nv_bfloat16 bf16;

// ---------------------------------------------------------------------------
// Scratch (static device globals)
// ---------------------------------------------------------------------------
__device__ bf16  g_wqkvh[QKV_C * DIM],  g_wqkvl[QKV_C * DIM];
__device__ bf16  g_wprjh[DIM * DIM],    g_wprjl[DIM * DIM];
__device__ bf16  g_w1h  [M1_PAD * DIM], g_w1l  [M1_PAD * DIM];
__device__ bf16  g_w2h  [DIM * HID_PAD],g_w2l  [DIM * HID_PAD];
__device__ float g_b1p  [M1_PAD];
__device__ float g_qkv  [(size_t)BATCH * QKV_C * HW];
__device__ float g_qkvdw[(size_t)BATCH * QKV_C * HW];
__device__ float g_ssq  [BATCH * 2 * DIM];
__device__ float g_part [BATCH * HEADS * 8 * CH * CH];
__device__ float g_attn [BATCH * HEADS * CH * CH];
__device__ bf16  g_aoh  [(size_t)BATCH * DIM * HW];
__device__ bf16  g_aol  [(size_t)BATCH * DIM * HW];
__device__ bf16  g_outh [(size_t)BATCH * DIM * HW];
__device__ bf16  g_outl [(size_t)BATCH * DIM * HW];
__device__ bf16  g_hidh [(size_t)BATCH * M1_PAD * HW];
__device__ bf16  g_hidl [(size_t)BATCH * M1_PAD * HW];

// ---------------------------------------------------------------------------
__device__ __forceinline__ float gelu_tanh(float x) {
    float x3 = x * x * x;
    return 0.5f * x * (1.0f + tanhf(0.7978845608028654f * (x + 0.044715f * x3)));
}
__device__ __forceinline__ void split2(float v, bf16& h, bf16& l) {
    h = __float2bfloat16(v);
    l = __float2bfloat16(v - __bfloat162float(h));
}
__device__ __forceinline__ uint32_t packbf(bf16 a, bf16 b) {
    return ((uint32_t)__bfloat16_as_ushort(b) << 16) | (uint32_t)__bfloat16_as_ushort(a);
}
// split 8 floats -> packed hi plane (4 uint32) + lo plane (4 uint32)
__device__ __forceinline__ void split_pack8(const float* f, uint32_t* hp, uint32_t* lp) {
#pragma unroll
    for (int q = 0; q < 4; q++) {
        bf16 h0, l0, h1, l1;
        split2(f[2 * q], h0, l0);
        split2(f[2 * q + 1], h1, l1);
        hp[q] = packbf(h0, h1);
        lp[q] = packbf(l0, l1);
    }
}

// ---------------------------------------------------------------------------
// PTX wrappers
// ---------------------------------------------------------------------------
__device__ __forceinline__ void ldsm_x4(uint32_t& r0, uint32_t& r1, uint32_t& r2,
                                        uint32_t& r3, uint32_t addr) {
    asm volatile("ldmatrix.sync.aligned.m8n8.x4.shared.b16 {%0,%1,%2,%3}, [%4];"
                 : "=r"(r0), "=r"(r1), "=r"(r2), "=r"(r3) : "r"(addr));
}
__device__ __forceinline__ void ldsm_x4_t(uint32_t& r0, uint32_t& r1, uint32_t& r2,
                                          uint32_t& r3, uint32_t addr) {
    asm volatile("ldmatrix.sync.aligned.m8n8.x4.trans.shared.b16 {%0,%1,%2,%3}, [%4];"
                 : "=r"(r0), "=r"(r1), "=r"(r2), "=r"(r3) : "r"(addr));
}
__device__ __forceinline__ void mma16816(float* d, const uint32_t* a,
                                         uint32_t b0, uint32_t b1) {
    asm volatile(
        "mma.sync.aligned.m16n8k16.row.col.f32.bf16.bf16.f32 "
        "{%0,%1,%2,%3}, {%4,%5,%6,%7}, {%8,%9}, {%0,%1,%2,%3};"
        : "+f"(d[0]), "+f"(d[1]), "+f"(d[2]), "+f"(d[3])
        : "r"(a[0]), "r"(a[1]), "r"(a[2]), "r"(a[3]), "r"(b0), "r"(b1));
}

// ---------------------------------------------------------------------------
// prep: split weights to bf16 hi/lo (with padding) + padded bias
// ---------------------------------------------------------------------------
#define PN1 (QKV_C * DIM)
#define PN2 (DIM * DIM)
#define PN3 (M1_PAD * DIM)
#define PN4 (DIM * HID_PAD)
#define PN5 (M1_PAD)
__global__ void prep_kernel(const float* __restrict__ wqkv, const float* __restrict__ wprj,
                            const float* __restrict__ w1,   const float* __restrict__ w2,
                            const float* __restrict__ b1)
{
    int i = blockIdx.x * blockDim.x + threadIdx.x;
    if (i < PN1) { split2(wqkv[i], g_wqkvh[i], g_wqkvl[i]); return; }
    i -= PN1;
    if (i < PN2) { split2(wprj[i], g_wprjh[i], g_wprjl[i]); return; }
    i -= PN2;
    if (i < PN3) {
        int r = i >> 8;
        float v = (r < HIDDEN) ? w1[i] : 0.f;
        split2(v, g_w1h[i], g_w1l[i]); return;
    }
    i -= PN3;
    if (i < PN4) {
        int r = i / HID_PAD, c = i - r * HID_PAD;
        float v = (c < HIDDEN) ? w2[r * HIDDEN + c] : 0.f;
        split2(v, g_w2h[i], g_w2l[i]); return;
    }
    i -= PN4;
    if (i < PN5) g_b1p[i] = (i < HIDDEN) ? b1[i] : 0.f;
}

// ---------------------------------------------------------------------------
// bf16x3 tensor-core GEMM: C[b] = A(MxK) @ B[b](KxN) + epilogue
// If SPLITB: B is fp32, split to hi/lo in-register during staging.
//   EPI 0 (QKV):  Cf = acc
//   EPI 1 (PROJ): v = acc + Res; Cf = v; (Ch,Cl) = split(v)
//   EPI 2 (MLP1): v = gelu(acc + bias); (Ch,Cl) = split(v)
//   EPI 3 (MLP2): Cf = acc + bias + Res  (Res may alias Cf)
// ---------------------------------------------------------------------------
template <int EPI, bool SPLITB>
__global__ __launch_bounds__(256)
void hgemm_kernel(const bf16* __restrict__ Ah, const bf16* __restrict__ Al,
                  const bf16* __restrict__ Bhg, const bf16* __restrict__ Blg,
                  const float* __restrict__ Bfg,
                  float* __restrict__ Cfg, bf16* __restrict__ Chg, bf16* __restrict__ Clg,
                  const float* __restrict__ bias, const float* __restrict__ Resg,
                  int M, int N, int K, int bStride, int mStrideC)
{
    const int batch = blockIdx.z;
    const size_t cOff = (size_t)batch * mStrideC * N;

    const int m0 = blockIdx.y * 128;
    const int n0 = blockIdx.x * 128;

    __shared__ __align__(16) bf16 sA[2][2][128][24];
    __shared__ __align__(16) bf16 sB[2][2][16][136];

    const int tid  = threadIdx.x;
    const int lane = tid & 31;
    const int warp = tid >> 5;
    const int wm = warp & 3;
    const int wn = warp >> 2;

    const uint32_t sA0 = (uint32_t)__cvta_generic_to_shared(&sA[0][0][0][0]);
    const uint32_t sB0 = (uint32_t)__cvta_generic_to_shared(&sB[0][0][0][0]);
    const uint32_t A_PL = 128 * 24 * 2, A_BUF = 2 * A_PL;
    const uint32_t B_PL = 16 * 136 * 2, B_BUF = 2 * B_PL;

    const uint32_t aAddr = sA0 + ((wm * 32 + (lane & 15)) * 24) * 2 + ((lane >> 4) * 16);
    const uint32_t bAddr = sB0 + ((lane & 15) * 136 + wn * 64 + (lane >> 4) * 8) * 2;

    const int am = tid >> 1, ahalf = tid & 1;
    const int bk = tid >> 4, bseg  = tid & 15;
    const bf16* gAh = Ah + (size_t)(m0 + am) * K + ahalf * 8;
    const bf16* gAl = Al + (size_t)(m0 + am) * K + ahalf * 8;
    const bf16* gBh; const bf16* gBl; const float* gBf;
    if (SPLITB) {
        gBf = Bfg + (size_t)batch * bStride + (size_t)bk * N + n0 + bseg * 8;
    } else {
        gBh = Bhg + (size_t)batch * bStride + (size_t)bk * N + n0 + bseg * 8;
        gBl = Blg + (size_t)batch * bStride + (size_t)bk * N + n0 + bseg * 8;
    }

    const int numKT = K >> 4;
    int4 rah, ral, rbh, rbl;
    float4 rf0, rf1;

    // preload chunk 0
    rah = *(const int4*)gAh;
    ral = *(const int4*)gAl;
    if (SPLITB) { rf0 = *(const float4*)gBf; rf1 = *((const float4*)gBf + 1); }
    else        { rbh = *(const int4*)gBh;   rbl = *(const int4*)gBl; }
    *(int4*)&sA[0][0][am][ahalf * 8] = rah;
    *(int4*)&sA[0][1][am][ahalf * 8] = ral;
    if (SPLITB) {
        float f[8] = {rf0.x, rf0.y, rf0.z, rf0.w, rf1.x, rf1.y, rf1.z, rf1.w};
        uint32_t hp[4], lp[4];
        split_pack8(f, hp, lp);
        *(int4*)&sB[0][0][bk][bseg * 8] = *(int4*)hp;
        *(int4*)&sB[0][1][bk][bseg * 8] = *(int4*)lp;
    } else {
        *(int4*)&sB[0][0][bk][bseg * 8] = rbh;
        *(int4*)&sB[0][1][bk][bseg * 8] = rbl;
    }
    __syncthreads();

    float acc[2][8][4];
#pragma unroll
    for (int i = 0; i < 2; i++)
#pragma unroll
        for (int j = 0; j < 8; j++)
#pragma unroll
            for (int q = 0; q < 4; q++) acc[i][j][q] = 0.f;

    for (int kt = 0; kt < numKT; ++kt) {
        const int buf = kt & 1;
        if (kt + 1 < numKT) {
            const int kb = (kt + 1) << 4;
            rah = *(const int4*)(gAh + kb);
            ral = *(const int4*)(gAl + kb);
            if (SPLITB) {
                rf0 = *(const float4*)(gBf + (size_t)kb * N);
                rf1 = *((const float4*)(gBf + (size_t)kb * N) + 1);
            } else {
                rbh = *(const int4*)(gBh + (size_t)kb * N);
                rbl = *(const int4*)(gBl + (size_t)kb * N);
            }
        }

        uint32_t ah[2][4], al[2][4];
        {
            const uint32_t ab = aAddr + buf * A_BUF;
            ldsm_x4(ah[0][0], ah[0][1], ah[0][2], ah[0][3], ab);
            ldsm_x4(ah[1][0], ah[1][1], ah[1][2], ah[1][3], ab + 16 * 24 * 2);
            ldsm_x4(al[0][0], al[0][1], al[0][2], al[0][3], ab + A_PL);
            ldsm_x4(al[1][0], al[1][1], al[1][2], al[1][3], ab + A_PL + 16 * 24 * 2);
        }
        const uint32_t bb = bAddr + buf * B_BUF;
#pragma unroll
        for (int j2 = 0; j2 < 4; j2++) {
            uint32_t bh0, bh1, bh2, bh3, bl0, bl1, bl2, bl3;
            ldsm_x4_t(bh0, bh1, bh2, bh3, bb + j2 * 32);
            ldsm_x4_t(bl0, bl1, bl2, bl3, bb + B_PL + j2 * 32);
            // issue grouped by term so same-acc RAW chains are distance-4
            mma16816(acc[0][2 * j2],     ah[0], bh0, bh1);
            mma16816(acc[1][2 * j2],     ah[1], bh0, bh1);
            mma16816(acc[0][2 * j2 + 1], ah[0], bh2, bh3);
            mma16816(acc[1][2 * j2 + 1], ah[1], bh2, bh3);
            mma16816(acc[0][2 * j2],     ah[0], bl0, bl1);
            mma16816(acc[1][2 * j2],     ah[1], bl0, bl1);
            mma16816(acc[0][2 * j2 + 1], ah[0], bl2, bl3);
            mma16816(acc[1][2 * j2 + 1], ah[1], bl2, bl3);
            mma16816(acc[0][2 * j2],     al[0], bh0, bh1);
            mma16816(acc[1][2 * j2],     al[1], bh0, bh1);
            mma16816(acc[0][2 * j2 + 1], al[0], bh2, bh3);
            mma16816(acc[1][2 * j2 + 1], al[1], bh2, bh3);
        }

        if (kt + 1 < numKT) {
            const int nb = buf ^ 1;
            *(int4*)&sA[nb][0][am][ahalf * 8] = rah;
            *(int4*)&sA[nb][1][am][ahalf * 8] = ral;
            if (SPLITB) {
                float f[8] = {rf0.x, rf0.y, rf0.z, rf0.w, rf1.x, rf1.y, rf1.z, rf1.w};
                uint32_t hp[4], lp[4];
                split_pack8(f, hp, lp);
                *(int4*)&sB[nb][0][bk][bseg * 8] = *(int4*)hp;
                *(int4*)&sB[nb][1][bk][bseg * 8] = *(int4*)lp;
            } else {
                *(int4*)&sB[nb][0][bk][bseg * 8] = rbh;
                *(int4*)&sB[nb][1][bk][bseg * 8] = rbl;
            }
        }
        __syncthreads();
    }

    // epilogue
    float* Cf = (EPI != 2) ? (Cfg + cOff) : nullptr;
    bf16*  Chp = (EPI == 1 || EPI == 2) ? (Chg + cOff) : nullptr;
    bf16*  Clp = (EPI == 1 || EPI == 2) ? (Clg + cOff) : nullptr;
    const float* R = (EPI == 1 || EPI == 3) ? (Resg + cOff) : nullptr;

    const int g = lane >> 2, t = lane & 3;
#pragma unroll
    for (int i = 0; i < 2; i++) {
#pragma unroll
        for (int half = 0; half < 2; half++) {
            const int r = m0 + wm * 32 + i * 16 + half * 8 + g;
            float bi = 0.f;
            if (EPI == 2 || EPI == 3) bi = bias[r];
#pragma unroll
            for (int j = 0; j < 8; j++) {
                const int c = n0 + wn * 64 + j * 8 + t * 2;
                float v0 = acc[i][j][half * 2 + 0];
                float v1 = acc[i][j][half * 2 + 1];
                const size_t idx = (size_t)r * N + c;
                if (EPI == 0) {
                    Cf[idx] = v0; Cf[idx + 1] = v1;
                } else if (EPI == 1) {
                    v0 += R[idx]; v1 += R[idx + 1];
                    Cf[idx] = v0; Cf[idx + 1] = v1;
                    bf16 h0, l0, h1, l1;
                    split2(v0, h0, l0); split2(v1, h1, l1);
                    *(uint32_t*)&Chp[idx] = packbf(h0, h1);
                    *(uint32_t*)&Clp[idx] = packbf(l0, l1);
                } else if (EPI == 2) {
                    v0 = gelu_tanh(v0 + bi); v1 = gelu_tanh(v1 + bi);
                    bf16 h0, l0, h1, l1;
                    split2(v0, h0, l0); split2(v1, h1, l1);
                    *(uint32_t*)&Chp[idx] = packbf(h0, h1);
                    *(uint32_t*)&Clp[idx] = packbf(l0, l1);
                } else {
                    v0 += bi + R[idx]; v1 += bi + R[idx + 1];
                    Cf[idx] = v0; Cf[idx + 1] = v1;
                }
            }
        }
    }
}

// ---------------------------------------------------------------------------
// Depthwise 3x3 conv, smem-tiled: one block per (b,ch) 64x64 plane.
// ---------------------------------------------------------------------------
__global__ __launch_bounds__(256)
void dwconv_kernel(const float* __restrict__ in, const float* __restrict__ w,
                   float* __restrict__ out, float* __restrict__ ssq)
{
    const int bc = blockIdx.x;
    const int b  = bc / QKV_C;
    const int ch = bc - b * QKV_C;
    const int tid = threadIdx.x;

    __shared__ float t[66][68];
    __shared__ float red[8];

    if (tid < 264) {
        if (tid < 68)       t[0][tid] = 0.f;
        else if (tid < 136) t[65][tid - 68] = 0.f;
        else if (tid < 200) t[tid - 136 + 1][0] = 0.f;
        else                t[tid - 200 + 1][65] = 0.f;
    }

    const float4* ip4 = (const float4*)(in + (size_t)bc * HW);
#pragma unroll
    for (int j = 0; j < 4; j++) {
        int idx = tid + j * 256;
        int h = idx >> 4, w4 = idx & 15;
        float4 v = ip4[idx];
        t[h + 1][w4 * 4 + 1] = v.x;
        t[h + 1][w4 * 4 + 2] = v.y;
        t[h + 1][w4 * 4 + 3] = v.z;
        t[h + 1][w4 * 4 + 4] = v.w;
    }

    const float* wp = w + ch * 9;
    float k0 = wp[0], k1 = wp[1], k2 = wp[2];
    float k3 = wp[3], k4 = wp[4], k5 = wp[5];
    float k6 = wp[6], k7 = wp[7], k8 = wp[8];
    __syncthreads();

    float4* op4 = (float4*)(out + (size_t)bc * HW);
    float ss = 0.f;

#pragma unroll
    for (int grp = 0; grp < 4; grp++) {
        const int n = grp * 1024 + tid * 4;
        const int h = n >> 6, w0 = n & 63;
        float s0 = 0.f, s1 = 0.f, s2 = 0.f, s3 = 0.f;
#pragma unroll
        for (int dh = 0; dh < 3; dh++) {
            const float* r = &t[h + dh][w0];
            float r0 = r[0], r1 = r[1], r2 = r[2], r3 = r[3], r4 = r[4], r5 = r[5];
            float ka = (dh == 0) ? k0 : (dh == 1) ? k3 : k6;
            float kb = (dh == 0) ? k1 : (dh == 1) ? k4 : k7;
            float kc = (dh == 0) ? k2 : (dh == 1) ? k5 : k8;
            s0 = fmaf(ka, r0, fmaf(kb, r1, fmaf(kc, r2, s0)));
            s1 = fmaf(ka, r1, fmaf(kb, r2, fmaf(kc, r3, s1)));
            s2 = fmaf(ka, r2, fmaf(kb, r3, fmaf(kc, r4, s2)));
            s3 = fmaf(ka, r3, fmaf(kb, r4, fmaf(kc, r5, s3)));
        }
        float4 o; o.x = s0; o.y = s1; o.z = s2; o.w = s3;
        op4[grp * 256 + tid] = o;
        ss += s0 * s0 + s1 * s1 + s2 * s2 + s3 * s3;
    }

    if (ch < 2 * DIM) {
#pragma unroll
        for (int o = 16; o; o >>= 1) ss += __shfl_down_sync(0xffffffffu, ss, o);
        if ((tid & 31) == 0) red[tid >> 5] = ss;
        __syncthreads();
        if (tid == 0) {
            float s = 0.f;
#pragma unroll
            for (int i = 0; i < 8; i++) s += red[i];
            ssq[b * 2 * DIM + ch] = s;
        }
    }
}

// ---------------------------------------------------------------------------
// Partial attention logits, register outer-product version.
// 256 threads = 4 j-slices x 64 threads; each thread owns a 4c x 4d tile.
// Per 4-j step: 8 x LDS.128 feed 64 FMA. Cross-slice reduce at block end.
// ---------------------------------------------------------------------------
__global__ __launch_bounds__(256)
void attn_partial_kernel(const float* __restrict__ qkvdw, float* __restrict__ part)
{
    const int split = blockIdx.x;
    const int bh = blockIdx.y;
    const int b = bh >> 3, head = bh & 7;

    const float* qp = qkvdw + ((size_t)(b * QKV_C + head * CH)) * HW;
    const float* kp = qkvdw + ((size_t)(b * QKV_C + DIM + head * CH)) * HW;

    __shared__ __align__(16) float qs[32][132];
    __shared__ __align__(16) float ks[32][132];
    __shared__ float sred[4][64][16];

    const int tid = threadIdx.x;
    const int slice = tid >> 6;
    const int t64 = tid & 63;
    const int c0 = (t64 & 7) * 4;
    const int d0 = (t64 >> 3) * 4;

    float acc[4][4];
#pragma unroll
    for (int i = 0; i < 4; i++)
#pragma unroll
        for (int q = 0; q < 4; q++) acc[i][q] = 0.f;

    for (int t = 0; t < 4; ++t) {
        const int n0 = split * 512 + t * 128;
        __syncthreads();
#pragma unroll
        for (int it = 0; it < 4; it++) {
            int idx = tid + it * 256;
            int row = idx >> 5, j4 = idx & 31;
            *(float4*)&qs[row][j4 * 4] = *(const float4*)&qp[(size_t)row * HW + n0 + j4 * 4];
            *(float4*)&ks[row][j4 * 4] = *(const float4*)&kp[(size_t)row * HW + n0 + j4 * 4];
        }
        __syncthreads();
#pragma unroll
        for (int jj = 0; jj < 32; jj += 4) {
            const int j = slice * 32 + jj;
            float4 qv[4], kv[4];
#pragma unroll
            for (int i = 0; i < 4; i++) qv[i] = *(const float4*)&qs[c0 + i][j];
#pragma unroll
            for (int q = 0; q < 4; q++) kv[q] = *(const float4*)&ks[d0 + q][j];
#pragma unroll
            for (int i = 0; i < 4; i++)
#pragma unroll
                for (int q = 0; q < 4; q++) {
                    acc[i][q] = fmaf(qv[i].x, kv[q].x, acc[i][q]);
                    acc[i][q] = fmaf(qv[i].y, kv[q].y, acc[i][q]);
                    acc[i][q] = fmaf(qv[i].z, kv[q].z, acc[i][q]);
                    acc[i][q] = fmaf(qv[i].w, kv[q].w, acc[i][q]);
                }
        }
    }

    // cross-slice reduction
#pragma unroll
    for (int i = 0; i < 4; i++)
#pragma unroll
        for (int q = 0; q < 4; q++) sred[slice][t64][i * 4 + q] = acc[i][q];
    __syncthreads();

    float* pp = part + ((size_t)(bh * 8 + split)) * (CH * CH);
#pragma unroll
    for (int qq = 0; qq < 4; qq++) {
        const int e = tid * 4 + qq;
        const int c = e >> 5, d = e & 31;
        const int t2 = (d >> 2) * 8 + (c >> 2);
        const int f = (c & 3) * 4 + (d & 3);
        pp[e] = sred[0][t2][f] + sred[1][t2][f] + sred[2][t2][f] + sred[3][t2][f];
    }
}

// ---------------------------------------------------------------------------
// Reduce partials, fold norms + temperature, softmax.
// ---------------------------------------------------------------------------
__global__ __launch_bounds__(256)
void attn_softmax_kernel(const float* __restrict__ part,
                         const float* __restrict__ ssq,
                         const float* __restrict__ temp,
                         float* __restrict__ attn)
{
    const int bh = blockIdx.x;
    const int b = bh >> 3, head = bh & 7;
    const int tid = threadIdx.x;

    __shared__ float S[32][33];
    __shared__ float fq[32], fk[32];

    if (tid < 64) {
        int isK = tid >> 5, c = tid & 31;
        int ch = isK ? (DIM + head * CH + c) : (head * CH + c);
        float s = ssq[b * 2 * DIM + ch];
        float f = 1.0f / fmaxf(sqrtf(s), 1e-12f);
        if (isK) fk[c] = f; else fq[c] = f;
    }
    __syncthreads();

    const float T = temp[head];
#pragma unroll
    for (int r = 0; r < 4; r++) {
        int e = tid + r * 256;
        int c = e >> 5, d = e & 31;
        float s = 0.f;
#pragma unroll
        for (int p = 0; p < 8; p++) s += part[((size_t)(bh * 8 + p)) * (CH * CH) + e];
        S[c][d] = s * fq[c] * fk[d] * T;
    }
    __syncthreads();

    if (tid < 32) {
        float m = -1e30f;
#pragma unroll
        for (int d = 0; d < 32; d++) m = fmaxf(m, S[tid][d]);
        float sum = 0.f;
        float e[32];
#pragma unroll
        for (int d = 0; d < 32; d++) { e[d] = expf(S[tid][d] - m); sum += e[d]; }
        float inv = 1.0f / sum;
        float* ap = attn + (size_t)bh * CH * CH + tid * CH;
#pragma unroll
        for (int d = 0; d < 32; d++) ap[d] = e[d] * inv;
    }
}

// ---------------------------------------------------------------------------
// Apply attention: out[c,n] = sum_d attn[c,d] * v[d,n]  -> bf16 hi/lo
// float2 pixels per thread, packed bf16x2 stores.
// ---------------------------------------------------------------------------
__global__ __launch_bounds__(256)
void attn_apply_kernel(const float* __restrict__ qkvdw,
                       const float* __restrict__ attn,
                       bf16* __restrict__ outh, bf16* __restrict__ outl)
{
    const int bh = blockIdx.y;
    const int b = bh >> 3, head = bh & 7;

    __shared__ float a[32][32];
    for (int i = threadIdx.x; i < 1024; i += 256)
        a[i >> 5][i & 31] = attn[(size_t)bh * 1024 + i];
    __syncthreads();

    const float2* vp2 = (const float2*)(qkvdw + ((size_t)(b * QKV_C + 2 * DIM + head * CH)) * HW);
    const size_t obase = ((size_t)(b * DIM + head * CH)) * HW;
    const int n2 = blockIdx.x * 256 + threadIdx.x;   // float2 index

    float2 o[32];
#pragma unroll
    for (int c = 0; c < 32; c++) { o[c].x = 0.f; o[c].y = 0.f; }
#pragma unroll
    for (int d = 0; d < 32; d++) {
        float2 vv = vp2[(size_t)d * (HW / 2) + n2];
#pragma unroll
        for (int c = 0; c < 32; c++) {
            o[c].x = fmaf(a[c][d], vv.x, o[c].x);
            o[c].y = fmaf(a[c][d], vv.y, o[c].y);
        }
    }
#pragma unroll
    for (int c = 0; c < 32; c++) {
        bf16 h0, l0, h1, l1;
        split2(o[c].x, h0, l0);
        split2(o[c].y, h1, l1);
        const size_t idx = obase + (size_t)c * HW + n2 * 2;
        *(uint32_t*)&outh[idx] = packbf(h0, h1);
        *(uint32_t*)&outl[idx] = packbf(l0, l1);
    }
}

// ---------------------------------------------------------------------------
extern "C" void kernel_launch(void* const* d_in, const int* in_sizes, int n_in,
                              void* d_out, int out_size)
{
    const float* x      = (const float*)d_in[0];
    const float* w_qkv  = (const float*)d_in[1];
    const float* w_dw   = (const float*)d_in[2];
    const float* temp   = (const float*)d_in[3];
    const float* w_proj = (const float*)d_in[4];
    const float* w_mlp1 = (const float*)d_in[5];
    const float* b_mlp1 = (const float*)d_in[6];
    const float* w_mlp2 = (const float*)d_in[7];
    const float* b_mlp2 = (const float*)d_in[8];
    float* out = (float*)d_out;

    bf16 *wqkvh, *wqkvl, *wprjh, *wprjl, *w1h, *w1l, *w2h, *w2l;
    bf16 *aoh, *aol, *outh, *outl, *hidh, *hidl;
    float *b1p, *qkv, *qkvdw, *ssq, *part, *attn;
    cudaGetSymbolAddress((void**)&wqkvh, g_wqkvh);
    cudaGetSymbolAddress((void**)&wqkvl, g_wqkvl);
    cudaGetSymbolAddress((void**)&wprjh, g_wprjh);
    cudaGetSymbolAddress((void**)&wprjl, g_wprjl);
    cudaGetSymbolAddress((void**)&w1h,   g_w1h);
    cudaGetSymbolAddress((void**)&w1l,   g_w1l);
    cudaGetSymbolAddress((void**)&w2h,   g_w2h);
    cudaGetSymbolAddress((void**)&w2l,   g_w2l);
    cudaGetSymbolAddress((void**)&b1p,   g_b1p);
    cudaGetSymbolAddress((void**)&qkv,   g_qkv);
    cudaGetSymbolAddress((void**)&qkvdw, g_qkvdw);
    cudaGetSymbolAddress((void**)&ssq,   g_ssq);
    cudaGetSymbolAddress((void**)&part,  g_part);
    cudaGetSymbolAddress((void**)&attn,  g_attn);
    cudaGetSymbolAddress((void**)&aoh,   g_aoh);
    cudaGetSymbolAddress((void**)&aol,   g_aol);
    cudaGetSymbolAddress((void**)&outh,  g_outh);
    cudaGetSymbolAddress((void**)&outl,  g_outl);
    cudaGetSymbolAddress((void**)&hidh,  g_hidh);
    cudaGetSymbolAddress((void**)&hidl,  g_hidl);

    // 0) weight splits + padded bias
    const int prepTotal = PN1 + PN2 + PN3 + PN4 + PN5;
    prep_kernel<<<(prepTotal + 255) / 256, 256>>>(w_qkv, w_proj, w_mlp1, w_mlp2, b_mlp1);

    // 1) qkv = w_qkv @ x  (x split in-register during staging)
    hgemm_kernel<0, true><<<dim3(HW / 128, QKV_C / 128, BATCH), 256>>>(
        wqkvh, wqkvl, nullptr, nullptr, x, qkv, nullptr, nullptr, nullptr, nullptr,
        QKV_C, HW, DIM, DIM * HW, QKV_C);

    // 2) depthwise 3x3 (smem-tiled) + full-plane sumsq
    dwconv_kernel<<<dim3(BATCH * QKV_C), 256>>>(qkv, w_dw, qkvdw, ssq);

    // 3) partial logits
    attn_partial_kernel<<<dim3(8, BATCH * HEADS), 256>>>(qkvdw, part);

    // 4) reduce + scale + softmax
    attn_softmax_kernel<<<dim3(BATCH * HEADS), 256>>>(part, ssq, temp, attn);

    // 5) apply attention -> bf16 hi/lo
    attn_apply_kernel<<<dim3(HW / 512, BATCH * HEADS), 256>>>(qkvdw, attn, aoh, aol);

    // 6) x1 = x + w_proj @ attnout -> d_out fp32 + hi/lo
    hgemm_kernel<1, false><<<dim3(HW / 128, DIM / 128, BATCH), 256>>>(
        wprjh, wprjl, aoh, aol, nullptr, out, outh, outl, nullptr, x,
        DIM, HW, DIM, DIM * HW, DIM);

    // 7) hidden = gelu(w1 @ x1 + b1) -> hi/lo
    hgemm_kernel<2, false><<<dim3(HW / 128, M1_PAD / 128, BATCH), 256>>>(
        w1h, w1l, outh, outl, nullptr, nullptr, hidh, hidl, b1p, nullptr,
        M1_PAD, HW, DIM, DIM * HW, M1_PAD);

    // 8) d_out = x1 + w2 @ hidden + b2  (in place)
    hgemm_kernel<3, false><<<dim3(HW / 128, DIM / 128, BATCH), 256>>>(
        w2h, w2l, hidh, hidl, nullptr, out, nullptr, nullptr, b_mlp2, out,
        DIM, HW, HID_PAD, M1_PAD * HW, DIM);
}